// round 1
// baseline (speedup 1.0000x reference)
#include <cuda_runtime.h>
#include <cuda_bf16.h>
#include <math.h>

// ---------------- problem constants ----------------
#define BB 2
#define SS 2048
#define DD 1024
#define HH 16
#define HSZ 64
#define FF 4096
#define MM (BB*SS)          // 4096 rows
#define QKVN (3*DD)         // 3072

// ---------------- scratch (static device globals; no allocation) ----------------
__device__ float g_h   [MM*DD];     // LN1 output
__device__ float g_wqkv[DD*QKVN];   // repacked [D, 3072]
__device__ float g_qkv [(size_t)MM*QKVN];
__device__ float g_ctx [MM*DD];
__device__ float g_x1  [MM*DD];     // post-attention residual
__device__ float g_h2  [MM*DD];     // LN2 output
__device__ float g_ff  [(size_t)MM*FF];

// ---------------- LayerNorm: one block per row, 256 threads ----------------
__global__ __launch_bounds__(256) void ln_kernel(const float* __restrict__ in,
                                                 const float* __restrict__ sc,
                                                 const float* __restrict__ bi,
                                                 float* __restrict__ out)
{
    int row = blockIdx.x;
    const float* x = in + (size_t)row * DD;
    float v[4];
    float s = 0.f, sq = 0.f;
#pragma unroll
    for (int i = 0; i < 4; i++) {
        v[i] = x[threadIdx.x + i*256];
        s  += v[i];
        sq += v[i]*v[i];
    }
#pragma unroll
    for (int off = 16; off; off >>= 1) {
        s  += __shfl_xor_sync(0xFFFFFFFFu, s,  off);
        sq += __shfl_xor_sync(0xFFFFFFFFu, sq, off);
    }
    __shared__ float ws[8], wq[8];
    int w = threadIdx.x >> 5, ln = threadIdx.x & 31;
    if (ln == 0) { ws[w] = s; wq[w] = sq; }
    __syncthreads();
    s = 0.f; sq = 0.f;
#pragma unroll
    for (int i = 0; i < 8; i++) { s += ws[i]; sq += wq[i]; }
    float mu  = s * (1.f/DD);
    float var = sq * (1.f/DD) - mu*mu;
    float r   = rsqrtf(var + 1e-5f);
    float* o = out + (size_t)row * DD;
#pragma unroll
    for (int i = 0; i < 4; i++) {
        int c = threadIdx.x + i*256;
        o[c] = (v[i] - mu) * r * sc[c] + bi[c];
    }
}

// ---------------- repack Wq/Wk/Wv [H,D,HS] -> [D, 3072] ----------------
__global__ __launch_bounds__(256) void repack_qkv(const float* __restrict__ Wq,
                                                  const float* __restrict__ Wk,
                                                  const float* __restrict__ Wv,
                                                  float* __restrict__ Wout)
{
    int idx = blockIdx.x * 256 + threadIdx.x;      // 0 .. 1M-1
    int h   = idx >> 16;                           // / (D*HS)
    int rem = idx & 65535;
    int d   = rem >> 6;
    int e   = rem & 63;
    int col = h*HSZ + e;
    size_t base = (size_t)d * QKVN;
    Wout[base          + col] = Wq[idx];
    Wout[base + DD     + col] = Wk[idx];
    Wout[base + 2*DD   + col] = Wv[idx];
}

// ---------------- SGEMM: C[M,N] = A[M,K] @ B[K,N] (+bias)(+res)(relu) ----------------
// 128x128 block tile, BK=8, 256 threads, 8x8 per thread.
template<bool BIAS, bool RES, bool RELU>
__global__ __launch_bounds__(256) void sgemm(const float* __restrict__ A,
                                             const float* __restrict__ B,
                                             const float* __restrict__ bias,
                                             const float* __restrict__ res,
                                             float* __restrict__ C,
                                             int M, int N, int K)
{
    __shared__ float As[8][128];
    __shared__ float Bs[8][128];
    int tid = threadIdx.x;
    int rowBlock = blockIdx.y * 128;
    int colBlock = blockIdx.x * 128;
    int tr = (tid >> 4) * 8;          // 0..120
    int tc = (tid & 15) * 8;

    int arow = tid >> 1;              // 0..127
    int acol = (tid & 1) * 4;         // 0 or 4
    int brow = tid >> 5;              // 0..7
    int bcol = (tid & 31) * 4;

    const float* Aptr = A + (size_t)(rowBlock + arow) * K + acol;
    const float* Bptr = B + (size_t)brow * N + colBlock + bcol;

    float acc[8][8];
#pragma unroll
    for (int i = 0; i < 8; i++)
#pragma unroll
        for (int j = 0; j < 8; j++) acc[i][j] = 0.f;

    for (int kb = 0; kb < K; kb += 8) {
        float4 av = *(const float4*)Aptr;
        float4 bv = *(const float4*)Bptr;
        As[acol+0][arow] = av.x;
        As[acol+1][arow] = av.y;
        As[acol+2][arow] = av.z;
        As[acol+3][arow] = av.w;
        *(float4*)&Bs[brow][bcol] = bv;
        __syncthreads();
#pragma unroll
        for (int k = 0; k < 8; k++) {
            float ra[8], rb[8];
#pragma unroll
            for (int i = 0; i < 8; i++) ra[i] = As[k][tr + i];
#pragma unroll
            for (int j = 0; j < 8; j++) rb[j] = Bs[k][tc + j];
#pragma unroll
            for (int i = 0; i < 8; i++)
#pragma unroll
                for (int j = 0; j < 8; j++)
                    acc[i][j] = fmaf(ra[i], rb[j], acc[i][j]);
        }
        __syncthreads();
        Aptr += 8;
        Bptr += (size_t)8 * N;
    }

#pragma unroll
    for (int i = 0; i < 8; i++) {
        int row = rowBlock + tr + i;
#pragma unroll
        for (int j = 0; j < 8; j++) {
            int col = colBlock + tc + j;
            float vv = acc[i][j];
            if (BIAS) vv += bias[col];
            if (RES)  vv += res[(size_t)row * N + col];
            if (RELU) vv = fmaxf(vv, 0.f);
            C[(size_t)row * N + col] = vv;
        }
    }
}

// ---------------- Flash attention (causal, online softmax) ----------------
// qkv layout: row m = b*S+s, cols [0,1024)=Q, [1024,2048)=K, [2048,3072)=V, col = h*64+e
// grid: (B*H, S/128), block: 128 threads, 1 query per thread.
__global__ __launch_bounds__(128) void attn_kernel(const float* __restrict__ qkv,
                                                   float* __restrict__ ctx)
{
    int bh = blockIdx.x;
    int b  = bh / HH, h = bh % HH;
    int qt = blockIdx.y;
    int t  = threadIdx.x;
    int s  = qt * 128 + t;

    const float scale = 0.03125f;   // D^-0.5 = 1/32

    float q[HSZ];
    {
        const float* qrow = qkv + ((size_t)(b*SS + s)) * QKVN + h*HSZ;
#pragma unroll
        for (int e = 0; e < HSZ; e += 4) {
            float4 qv = *(const float4*)(qrow + e);
            q[e+0] = qv.x * scale; q[e+1] = qv.y * scale;
            q[e+2] = qv.z * scale; q[e+3] = qv.w * scale;
        }
    }

    float o[HSZ];
#pragma unroll
    for (int e = 0; e < HSZ; e++) o[e] = 0.f;
    float m = -1e30f, l = 0.f;

    __shared__ float Ks[64][64];
    __shared__ float Vs[64][64];

    int ntiles = 2*qt + 2;
    int r  = t >> 1;
    int c0 = (t & 1) * 32;

    for (int kt = 0; kt < ntiles; kt++) {
        size_t krowbase = ((size_t)(b*SS + kt*64 + r)) * QKVN + h*HSZ + c0;
        const float* krow = qkv + krowbase + DD;
        const float* vrow = qkv + krowbase + 2*DD;
#pragma unroll
        for (int i = 0; i < 8; i++) {
            *(float4*)&Ks[r][c0 + i*4] = ((const float4*)krow)[i];
            *(float4*)&Vs[r][c0 + i*4] = ((const float4*)vrow)[i];
        }
        __syncthreads();

        int jmax = s - kt*64 + 1;
        if (jmax > 64) jmax = 64;
        for (int j = 0; j < jmax; j++) {
            float sv0 = 0.f, sv1 = 0.f, sv2 = 0.f, sv3 = 0.f;
#pragma unroll
            for (int e = 0; e < HSZ; e += 4) {
                sv0 = fmaf(q[e+0], Ks[j][e+0], sv0);
                sv1 = fmaf(q[e+1], Ks[j][e+1], sv1);
                sv2 = fmaf(q[e+2], Ks[j][e+2], sv2);
                sv3 = fmaf(q[e+3], Ks[j][e+3], sv3);
            }
            float sv = (sv0 + sv1) + (sv2 + sv3);
            if (sv <= m) {
                float p = __expf(sv - m);
                l += p;
#pragma unroll
                for (int e = 0; e < HSZ; e++) o[e] = fmaf(p, Vs[j][e], o[e]);
            } else {
                float c = __expf(m - sv);
                m = sv;
                l = l*c + 1.f;
#pragma unroll
                for (int e = 0; e < HSZ; e++) o[e] = fmaf(o[e], c, Vs[j][e]);
            }
        }
        __syncthreads();
    }

    float inv = 1.f / l;
    float* orow = ctx + ((size_t)(b*SS + s)) * DD + h*HSZ;
#pragma unroll
    for (int e = 0; e < HSZ; e += 4) {
        float4 ov;
        ov.x = o[e+0]*inv; ov.y = o[e+1]*inv;
        ov.z = o[e+2]*inv; ov.w = o[e+3]*inv;
        *(float4*)(orow + e) = ov;
    }
}

// ---------------- host launcher ----------------
extern "C" void kernel_launch(void* const* d_in, const int* in_sizes, int n_in,
                              void* d_out, int out_size)
{
    const float* x         = (const float*)d_in[0];
    const float* ln1_scale = (const float*)d_in[1];
    const float* ln1_bias  = (const float*)d_in[2];
    const float* Wq        = (const float*)d_in[3];
    const float* Wk        = (const float*)d_in[4];
    const float* Wv        = (const float*)d_in[5];
    const float* Wo        = (const float*)d_in[6];
    const float* bo        = (const float*)d_in[7];
    const float* ln2_scale = (const float*)d_in[8];
    const float* ln2_bias  = (const float*)d_in[9];
    const float* W1        = (const float*)d_in[10];
    const float* b1        = (const float*)d_in[11];
    const float* W2        = (const float*)d_in[12];
    const float* b2        = (const float*)d_in[13];
    float* out = (float*)d_out;

    float *h, *wqkv, *qkv, *ctx, *x1, *h2, *ff;
    cudaGetSymbolAddress((void**)&h,    g_h);
    cudaGetSymbolAddress((void**)&wqkv, g_wqkv);
    cudaGetSymbolAddress((void**)&qkv,  g_qkv);
    cudaGetSymbolAddress((void**)&ctx,  g_ctx);
    cudaGetSymbolAddress((void**)&x1,   g_x1);
    cudaGetSymbolAddress((void**)&h2,   g_h2);
    cudaGetSymbolAddress((void**)&ff,   g_ff);

    // LN1
    ln_kernel<<<MM, 256>>>(x, ln1_scale, ln1_bias, h);
    // repack QKV weights
    repack_qkv<<<(HH*DD*HSZ)/256, 256>>>(Wq, Wk, Wv, wqkv);
    // QKV projection: [4096,1024] @ [1024,3072]
    sgemm<false,false,false><<<dim3(QKVN/128, MM/128), 256>>>(h, wqkv, nullptr, nullptr, qkv, MM, QKVN, DD);
    // attention
    attn_kernel<<<dim3(BB*HH, SS/128), 128>>>(qkv, ctx);
    // output projection + bias + residual x
    sgemm<true,true,false><<<dim3(DD/128, MM/128), 256>>>(ctx, Wo, bo, x, x1, MM, DD, DD);
    // LN2
    ln_kernel<<<MM, 256>>>(x1, ln2_scale, ln2_bias, h2);
    // FF1 + relu
    sgemm<true,false,true><<<dim3(FF/128, MM/128), 256>>>(h2, W1, b1, nullptr, ff, MM, FF, DD);
    // FF2 + bias + residual x1 -> out
    sgemm<true,true,false><<<dim3(DD/128, MM/128), 256>>>(ff, W2, b2, x1, out, MM, DD, FF);
}

// round 2
// speedup vs baseline: 1.1728x; 1.1728x over previous
#include <cuda_runtime.h>
#include <cuda_bf16.h>
#include <mma.h>
#include <math.h>

using namespace nvcuda;

// ---------------- problem constants ----------------
#define BB 2
#define SS 2048
#define DD 1024
#define HH 16
#define HSZ 64
#define FF 4096
#define MM (BB*SS)          // 4096 rows
#define QKVN (3*DD)         // 3072

// ---------------- scratch (static device globals; no allocation) ----------------
__device__ float g_h   [MM*DD];     // LN1 output
__device__ float g_wqkv[DD*QKVN];   // repacked [D, 3072]
__device__ float g_qkv [(size_t)MM*QKVN];
__device__ float g_ctx [MM*DD];
__device__ float g_x1  [MM*DD];     // post-attention residual
__device__ float g_h2  [MM*DD];     // LN2 output
__device__ float g_ff  [(size_t)MM*FF];

// ---------------- LayerNorm: one block per row, 256 threads ----------------
__global__ __launch_bounds__(256) void ln_kernel(const float* __restrict__ in,
                                                 const float* __restrict__ sc,
                                                 const float* __restrict__ bi,
                                                 float* __restrict__ out)
{
    int row = blockIdx.x;
    const float* x = in + (size_t)row * DD;
    float v[4];
    float s = 0.f, sq = 0.f;
#pragma unroll
    for (int i = 0; i < 4; i++) {
        v[i] = x[threadIdx.x + i*256];
        s  += v[i];
        sq += v[i]*v[i];
    }
#pragma unroll
    for (int off = 16; off; off >>= 1) {
        s  += __shfl_xor_sync(0xFFFFFFFFu, s,  off);
        sq += __shfl_xor_sync(0xFFFFFFFFu, sq, off);
    }
    __shared__ float ws[8], wq[8];
    int w = threadIdx.x >> 5, ln = threadIdx.x & 31;
    if (ln == 0) { ws[w] = s; wq[w] = sq; }
    __syncthreads();
    s = 0.f; sq = 0.f;
#pragma unroll
    for (int i = 0; i < 8; i++) { s += ws[i]; sq += wq[i]; }
    float mu  = s * (1.f/DD);
    float var = sq * (1.f/DD) - mu*mu;
    float r   = rsqrtf(var + 1e-5f);
    float* o = out + (size_t)row * DD;
#pragma unroll
    for (int i = 0; i < 4; i++) {
        int c = threadIdx.x + i*256;
        o[c] = (v[i] - mu) * r * sc[c] + bi[c];
    }
}

// ---------------- repack Wq/Wk/Wv [H,D,HS] -> [D, 3072] ----------------
__global__ __launch_bounds__(256) void repack_qkv(const float* __restrict__ Wq,
                                                  const float* __restrict__ Wk,
                                                  const float* __restrict__ Wv,
                                                  float* __restrict__ Wout)
{
    int idx = blockIdx.x * 256 + threadIdx.x;      // 0 .. 1M-1
    int h   = idx >> 16;                           // / (D*HS)
    int rem = idx & 65535;
    int d   = rem >> 6;
    int e   = rem & 63;
    int col = h*HSZ + e;
    size_t base = (size_t)d * QKVN;
    Wout[base          + col] = Wq[idx];
    Wout[base + DD     + col] = Wk[idx];
    Wout[base + 2*DD   + col] = Wv[idx];
}

// ---------------- TF32 tensor-core GEMM ----------------
// C[M,N] = A[M,K] @ B[K,N] (+bias)(+res)(relu)
// 128x128 block tile, BK=16, 256 threads (8 warps, 4x2), warp tile 32x64.
// wmma m16n16k8 tf32. TF32 conversion (RN) happens once at smem-store time.
#define APAD 20    // ldm for As (multiple of 4 floats)
#define BPAD 136   // ldm for Bs
#define CPAD 20    // ldm for epilogue staging

template<bool BIAS, bool RES, bool RELU>
__global__ __launch_bounds__(256) void gemm_tf32(const float* __restrict__ A,
                                                 const float* __restrict__ B,
                                                 const float* __restrict__ bias,
                                                 const float* __restrict__ res,
                                                 float* __restrict__ C,
                                                 int M, int N, int K)
{
    __shared__ float As[128][APAD];
    __shared__ float Bs[16][BPAD];
    __shared__ float cbuf[8][16][CPAD];

    int tid  = threadIdx.x;
    int w    = tid >> 5;
    int lane = tid & 31;
    int wm   = w & 3;          // 0..3: 32-row slice
    int wn   = w >> 2;         // 0..1: 64-col slice
    int rowBlock = blockIdx.y * 128;
    int colBlock = blockIdx.x * 128;

    wmma::fragment<wmma::accumulator, 16, 16, 8, float> acc[2][4];
#pragma unroll
    for (int i = 0; i < 2; i++)
#pragma unroll
        for (int j = 0; j < 4; j++) wmma::fill_fragment(acc[i][j], 0.f);

    const float* Ag = A + (size_t)rowBlock * K;
    const float* Bg = B + colBlock;

    // per-thread load coords (2 float4 each for A and B per k-tile)
    int idx0 = tid * 2;
    int ar0 = idx0 >> 2,  ac0 = (idx0 & 3) * 4;
    int ar1 = (idx0+1) >> 2, ac1 = ((idx0+1) & 3) * 4;
    int bk0 = idx0 >> 5,  bn0 = (idx0 & 31) * 4;
    int bk1 = (idx0+1) >> 5, bn1 = ((idx0+1) & 31) * 4;

    for (int kb = 0; kb < K; kb += 16) {
        float4 av0 = *(const float4*)(Ag + (size_t)ar0 * K + kb + ac0);
        float4 av1 = *(const float4*)(Ag + (size_t)ar1 * K + kb + ac1);
        float4 bv0 = *(const float4*)(Bg + (size_t)(kb + bk0) * N + bn0);
        float4 bv1 = *(const float4*)(Bg + (size_t)(kb + bk1) * N + bn1);

        As[ar0][ac0+0] = wmma::__float_to_tf32(av0.x);
        As[ar0][ac0+1] = wmma::__float_to_tf32(av0.y);
        As[ar0][ac0+2] = wmma::__float_to_tf32(av0.z);
        As[ar0][ac0+3] = wmma::__float_to_tf32(av0.w);
        As[ar1][ac1+0] = wmma::__float_to_tf32(av1.x);
        As[ar1][ac1+1] = wmma::__float_to_tf32(av1.y);
        As[ar1][ac1+2] = wmma::__float_to_tf32(av1.z);
        As[ar1][ac1+3] = wmma::__float_to_tf32(av1.w);
        Bs[bk0][bn0+0] = wmma::__float_to_tf32(bv0.x);
        Bs[bk0][bn0+1] = wmma::__float_to_tf32(bv0.y);
        Bs[bk0][bn0+2] = wmma::__float_to_tf32(bv0.z);
        Bs[bk0][bn0+3] = wmma::__float_to_tf32(bv0.w);
        Bs[bk1][bn1+0] = wmma::__float_to_tf32(bv1.x);
        Bs[bk1][bn1+1] = wmma::__float_to_tf32(bv1.y);
        Bs[bk1][bn1+2] = wmma::__float_to_tf32(bv1.z);
        Bs[bk1][bn1+3] = wmma::__float_to_tf32(bv1.w);
        __syncthreads();

#pragma unroll
        for (int ks = 0; ks < 2; ks++) {
            wmma::fragment<wmma::matrix_a, 16, 16, 8, wmma::precision::tf32, wmma::row_major> af[2];
            wmma::fragment<wmma::matrix_b, 16, 16, 8, wmma::precision::tf32, wmma::row_major> bf[4];
#pragma unroll
            for (int i = 0; i < 2; i++)
                wmma::load_matrix_sync(af[i], &As[wm*32 + i*16][ks*8], APAD);
#pragma unroll
            for (int j = 0; j < 4; j++)
                wmma::load_matrix_sync(bf[j], &Bs[ks*8][wn*64 + j*16], BPAD);
#pragma unroll
            for (int i = 0; i < 2; i++)
#pragma unroll
                for (int j = 0; j < 4; j++)
                    wmma::mma_sync(acc[i][j], af[i], bf[j], acc[i][j]);
        }
        __syncthreads();
    }

    // epilogue: stage each 16x16 frag through smem, apply postops
    int er = lane >> 1;          // 0..15
    int ec = (lane & 1) * 8;     // 0 or 8
#pragma unroll
    for (int i = 0; i < 2; i++) {
#pragma unroll
        for (int j = 0; j < 4; j++) {
            wmma::store_matrix_sync(&cbuf[w][0][0], acc[i][j], CPAD, wmma::mem_row_major);
            __syncwarp();
            int row = rowBlock + wm*32 + i*16 + er;
            int col = colBlock + wn*64 + j*16 + ec;
            size_t obase = (size_t)row * N + col;
#pragma unroll
            for (int c = 0; c < 8; c++) {
                float vv = cbuf[w][er][ec + c];
                if (BIAS) vv += bias[col + c];
                if (RES)  vv += res[obase + c];
                if (RELU) vv = fmaxf(vv, 0.f);
                C[obase + c] = vv;
            }
            __syncwarp();
        }
    }
}

// ---------------- Flash attention (causal, online softmax) ----------------
__global__ __launch_bounds__(128) void attn_kernel(const float* __restrict__ qkv,
                                                   float* __restrict__ ctx)
{
    int bh = blockIdx.x;
    int b  = bh / HH, h = bh % HH;
    int qt = blockIdx.y;
    int t  = threadIdx.x;
    int s  = qt * 128 + t;

    const float scale = 0.03125f;   // D^-0.5 = 1/32

    float q[HSZ];
    {
        const float* qrow = qkv + ((size_t)(b*SS + s)) * QKVN + h*HSZ;
#pragma unroll
        for (int e = 0; e < HSZ; e += 4) {
            float4 qv = *(const float4*)(qrow + e);
            q[e+0] = qv.x * scale; q[e+1] = qv.y * scale;
            q[e+2] = qv.z * scale; q[e+3] = qv.w * scale;
        }
    }

    float o[HSZ];
#pragma unroll
    for (int e = 0; e < HSZ; e++) o[e] = 0.f;
    float m = -1e30f, l = 0.f;

    __shared__ float Ks[64][64];
    __shared__ float Vs[64][64];

    int ntiles = 2*qt + 2;
    int r  = t >> 1;
    int c0 = (t & 1) * 32;

    for (int kt = 0; kt < ntiles; kt++) {
        size_t krowbase = ((size_t)(b*SS + kt*64 + r)) * QKVN + h*HSZ + c0;
        const float* krow = qkv + krowbase + DD;
        const float* vrow = qkv + krowbase + 2*DD;
#pragma unroll
        for (int i = 0; i < 8; i++) {
            *(float4*)&Ks[r][c0 + i*4] = ((const float4*)krow)[i];
            *(float4*)&Vs[r][c0 + i*4] = ((const float4*)vrow)[i];
        }
        __syncthreads();

        int jmax = s - kt*64 + 1;
        if (jmax > 64) jmax = 64;
        for (int j = 0; j < jmax; j++) {
            float sv0 = 0.f, sv1 = 0.f, sv2 = 0.f, sv3 = 0.f;
#pragma unroll
            for (int e = 0; e < HSZ; e += 4) {
                sv0 = fmaf(q[e+0], Ks[j][e+0], sv0);
                sv1 = fmaf(q[e+1], Ks[j][e+1], sv1);
                sv2 = fmaf(q[e+2], Ks[j][e+2], sv2);
                sv3 = fmaf(q[e+3], Ks[j][e+3], sv3);
            }
            float sv = (sv0 + sv1) + (sv2 + sv3);
            if (sv <= m) {
                float p = __expf(sv - m);
                l += p;
#pragma unroll
                for (int e = 0; e < HSZ; e++) o[e] = fmaf(p, Vs[j][e], o[e]);
            } else {
                float c = __expf(m - sv);
                m = sv;
                l = l*c + 1.f;
#pragma unroll
                for (int e = 0; e < HSZ; e++) o[e] = fmaf(o[e], c, Vs[j][e]);
            }
        }
        __syncthreads();
    }

    float inv = 1.f / l;
    float* orow = ctx + ((size_t)(b*SS + s)) * DD + h*HSZ;
#pragma unroll
    for (int e = 0; e < HSZ; e += 4) {
        float4 ov;
        ov.x = o[e+0]*inv; ov.y = o[e+1]*inv;
        ov.z = o[e+2]*inv; ov.w = o[e+3]*inv;
        *(float4*)(orow + e) = ov;
    }
}

// ---------------- host launcher ----------------
extern "C" void kernel_launch(void* const* d_in, const int* in_sizes, int n_in,
                              void* d_out, int out_size)
{
    const float* x         = (const float*)d_in[0];
    const float* ln1_scale = (const float*)d_in[1];
    const float* ln1_bias  = (const float*)d_in[2];
    const float* Wq        = (const float*)d_in[3];
    const float* Wk        = (const float*)d_in[4];
    const float* Wv        = (const float*)d_in[5];
    const float* Wo        = (const float*)d_in[6];
    const float* bo        = (const float*)d_in[7];
    const float* ln2_scale = (const float*)d_in[8];
    const float* ln2_bias  = (const float*)d_in[9];
    const float* W1        = (const float*)d_in[10];
    const float* b1        = (const float*)d_in[11];
    const float* W2        = (const float*)d_in[12];
    const float* b2        = (const float*)d_in[13];
    float* out = (float*)d_out;

    float *h, *wqkv, *qkv, *ctx, *x1, *h2, *ff;
    cudaGetSymbolAddress((void**)&h,    g_h);
    cudaGetSymbolAddress((void**)&wqkv, g_wqkv);
    cudaGetSymbolAddress((void**)&qkv,  g_qkv);
    cudaGetSymbolAddress((void**)&ctx,  g_ctx);
    cudaGetSymbolAddress((void**)&x1,   g_x1);
    cudaGetSymbolAddress((void**)&h2,   g_h2);
    cudaGetSymbolAddress((void**)&ff,   g_ff);

    // LN1
    ln_kernel<<<MM, 256>>>(x, ln1_scale, ln1_bias, h);
    // repack QKV weights
    repack_qkv<<<(HH*DD*HSZ)/256, 256>>>(Wq, Wk, Wv, wqkv);
    // QKV projection: [4096,1024] @ [1024,3072]
    gemm_tf32<false,false,false><<<dim3(QKVN/128, MM/128), 256>>>(h, wqkv, nullptr, nullptr, qkv, MM, QKVN, DD);
    // attention
    attn_kernel<<<dim3(BB*HH, SS/128), 128>>>(qkv, ctx);
    // output projection + bias + residual x
    gemm_tf32<true,true,false><<<dim3(DD/128, MM/128), 256>>>(ctx, Wo, bo, x, x1, MM, DD, DD);
    // LN2
    ln_kernel<<<MM, 256>>>(x1, ln2_scale, ln2_bias, h2);
    // FF1 + relu
    gemm_tf32<true,false,true><<<dim3(FF/128, MM/128), 256>>>(h2, W1, b1, nullptr, ff, MM, FF, DD);
    // FF2 + bias + residual x1 -> out
    gemm_tf32<true,true,false><<<dim3(DD/128, MM/128), 256>>>(ff, W2, b2, x1, out, MM, DD, FF);
}

// round 3
// speedup vs baseline: 1.3123x; 1.1190x over previous
#include <cuda_runtime.h>
#include <cuda_bf16.h>
#include <mma.h>
#include <math.h>

using namespace nvcuda;

// ---------------- problem constants ----------------
#define BB 2
#define SS 2048
#define DD 1024
#define HH 16
#define HSZ 64
#define FF 4096
#define MM (BB*SS)          // 4096 rows
#define QKVN (3*DD)         // 3072

// ---------------- scratch (static device globals; no allocation) ----------------
__device__ float g_h   [MM*DD];     // LN1 output (tf32-rounded)
__device__ float g_wqkv[DD*QKVN];   // repacked [D, 3072] (tf32-rounded)
__device__ float g_qkv [(size_t)MM*QKVN];
__device__ float g_ctx [MM*DD];     // attention out (tf32-rounded)
__device__ float g_x1  [MM*DD];     // post-attention residual (fp32)
__device__ float g_h2  [MM*DD];     // LN2 output (tf32-rounded)
__device__ float g_ff  [(size_t)MM*FF];  // FF1 out (tf32-rounded)
__device__ float g_wo  [DD*DD];     // tf32-rounded weights
__device__ float g_w1  [DD*FF];
__device__ float g_w2  [FF*DD];

// ---------------- cp.async helpers ----------------
__device__ __forceinline__ void cp16(void* smem, const void* gmem) {
    unsigned s = (unsigned)__cvta_generic_to_shared(smem);
    asm volatile("cp.async.cg.shared.global [%0], [%1], 16;\n" :: "r"(s), "l"(gmem));
}
#define CP_COMMIT asm volatile("cp.async.commit_group;\n" ::: "memory")
#define CP_WAIT1  asm volatile("cp.async.wait_group 1;\n" ::: "memory")
#define CP_WAIT0  asm volatile("cp.async.wait_group 0;\n" ::: "memory")

// ---------------- LayerNorm: one block per row, 256 threads, tf32-rounded out ----------------
__global__ __launch_bounds__(256) void ln_kernel(const float* __restrict__ in,
                                                 const float* __restrict__ sc,
                                                 const float* __restrict__ bi,
                                                 float* __restrict__ out)
{
    int row = blockIdx.x;
    const float* x = in + (size_t)row * DD;
    float v[4];
    float s = 0.f, sq = 0.f;
#pragma unroll
    for (int i = 0; i < 4; i++) {
        v[i] = x[threadIdx.x + i*256];
        s  += v[i];
        sq += v[i]*v[i];
    }
#pragma unroll
    for (int off = 16; off; off >>= 1) {
        s  += __shfl_xor_sync(0xFFFFFFFFu, s,  off);
        sq += __shfl_xor_sync(0xFFFFFFFFu, sq, off);
    }
    __shared__ float ws[8], wq[8];
    int w = threadIdx.x >> 5, ln = threadIdx.x & 31;
    if (ln == 0) { ws[w] = s; wq[w] = sq; }
    __syncthreads();
    s = 0.f; sq = 0.f;
#pragma unroll
    for (int i = 0; i < 8; i++) { s += ws[i]; sq += wq[i]; }
    float mu  = s * (1.f/DD);
    float var = sq * (1.f/DD) - mu*mu;
    float r   = rsqrtf(var + 1e-5f);
    float* o = out + (size_t)row * DD;
#pragma unroll
    for (int i = 0; i < 4; i++) {
        int c = threadIdx.x + i*256;
        o[c] = wmma::__float_to_tf32((v[i] - mu) * r * sc[c] + bi[c]);
    }
}

// ---------------- repack Wq/Wk/Wv [H,D,HS] -> [D, 3072], tf32-rounded ----------------
__global__ __launch_bounds__(256) void repack_qkv(const float* __restrict__ Wq,
                                                  const float* __restrict__ Wk,
                                                  const float* __restrict__ Wv,
                                                  float* __restrict__ Wout)
{
    int idx = blockIdx.x * 256 + threadIdx.x;      // 0 .. 1M-1
    int h   = idx >> 16;
    int rem = idx & 65535;
    int d   = rem >> 6;
    int e   = rem & 63;
    int col = h*HSZ + e;
    size_t base = (size_t)d * QKVN;
    Wout[base          + col] = wmma::__float_to_tf32(Wq[idx]);
    Wout[base + DD     + col] = wmma::__float_to_tf32(Wk[idx]);
    Wout[base + 2*DD   + col] = wmma::__float_to_tf32(Wv[idx]);
}

// ---------------- elementwise RN round to tf32 (float4) ----------------
__global__ __launch_bounds__(256) void round_tf32_k(const float* __restrict__ in,
                                                    float* __restrict__ out)
{
    int i = blockIdx.x * 256 + threadIdx.x;
    float4 v = ((const float4*)in)[i];
    v.x = wmma::__float_to_tf32(v.x);
    v.y = wmma::__float_to_tf32(v.y);
    v.z = wmma::__float_to_tf32(v.z);
    v.w = wmma::__float_to_tf32(v.w);
    ((float4*)out)[i] = v;
}

// ---------------- TF32 tensor-core GEMM, cp.async double-buffered ----------------
// C[M,N] = A[M,K] @ B[K,N] (+bias)(+res)(relu)(round-out)
// 128x128 block tile, BK=16, 256 threads (8 warps 4x2), warp tile 32x64.
// Inputs must already be tf32-rounded.
#define APAD 20
#define BPAD 132
#define CPAD 20

template<bool BIAS, bool RES, bool RELU, bool ROUND>
__global__ __launch_bounds__(256) void gemm_tf32(const float* __restrict__ A,
                                                 const float* __restrict__ B,
                                                 const float* __restrict__ bias,
                                                 const float* __restrict__ res,
                                                 float* __restrict__ C,
                                                 int M, int N, int K)
{
    __shared__ float As[2][128][APAD];
    __shared__ float Bs[2][16][BPAD];
    __shared__ float cbuf[8][16][CPAD];

    int tid  = threadIdx.x;
    int w    = tid >> 5;
    int lane = tid & 31;
    int wm   = w & 3;          // 0..3: 32-row slice
    int wn   = w >> 2;         // 0..1: 64-col slice
    int rowBlock = blockIdx.y * 128;
    int colBlock = blockIdx.x * 128;

    const float* Ag = A + (size_t)rowBlock * K;
    const float* Bg = B + colBlock;

    // A tile: 128x16 = 512 float4 chunks; B tile: 16x128 = 512 chunks. 2 each per thread.
    int a_r0 = tid >> 1,           a_c0 = (tid & 1) * 8;        // two float4 at c0, c0+4
    int b_r0 = tid >> 4,           b_c0 = (tid & 15) * 8;       // rows 0..15, two float4

    wmma::fragment<wmma::accumulator, 16, 16, 8, float> acc[2][4];
#pragma unroll
    for (int i = 0; i < 2; i++)
#pragma unroll
        for (int j = 0; j < 4; j++) wmma::fill_fragment(acc[i][j], 0.f);

    // prefetch tile 0
    {
        cp16(&As[0][a_r0][a_c0],   Ag + (size_t)a_r0 * K + a_c0);
        cp16(&As[0][a_r0][a_c0+4], Ag + (size_t)a_r0 * K + a_c0 + 4);
        cp16(&Bs[0][b_r0][b_c0],   Bg + (size_t)b_r0 * N + b_c0);
        cp16(&Bs[0][b_r0][b_c0+4], Bg + (size_t)b_r0 * N + b_c0 + 4);
        CP_COMMIT;
    }

    int nIter = K >> 4;
    for (int kt = 0; kt < nIter; kt++) {
        int buf = kt & 1;
        if (kt + 1 < nIter) {
            int kb = (kt + 1) << 4;
            cp16(&As[buf^1][a_r0][a_c0],   Ag + (size_t)a_r0 * K + kb + a_c0);
            cp16(&As[buf^1][a_r0][a_c0+4], Ag + (size_t)a_r0 * K + kb + a_c0 + 4);
            cp16(&Bs[buf^1][b_r0][b_c0],   Bg + (size_t)(kb + b_r0) * N + b_c0);
            cp16(&Bs[buf^1][b_r0][b_c0+4], Bg + (size_t)(kb + b_r0) * N + b_c0 + 4);
            CP_COMMIT;
            CP_WAIT1;
        } else {
            CP_WAIT0;
        }
        __syncthreads();

#pragma unroll
        for (int ks = 0; ks < 2; ks++) {
            wmma::fragment<wmma::matrix_a, 16, 16, 8, wmma::precision::tf32, wmma::row_major> af[2];
            wmma::fragment<wmma::matrix_b, 16, 16, 8, wmma::precision::tf32, wmma::row_major> bf[4];
#pragma unroll
            for (int i = 0; i < 2; i++)
                wmma::load_matrix_sync(af[i], &As[buf][wm*32 + i*16][ks*8], APAD);
#pragma unroll
            for (int j = 0; j < 4; j++)
                wmma::load_matrix_sync(bf[j], &Bs[buf][ks*8][wn*64 + j*16], BPAD);
#pragma unroll
            for (int i = 0; i < 2; i++)
#pragma unroll
                for (int j = 0; j < 4; j++)
                    wmma::mma_sync(acc[i][j], af[i], bf[j], acc[i][j]);
        }
        __syncthreads();
    }

    // epilogue: stage each 16x16 frag through smem, apply postops
    int er = lane >> 1;          // 0..15
    int ec = (lane & 1) * 8;     // 0 or 8
#pragma unroll
    for (int i = 0; i < 2; i++) {
#pragma unroll
        for (int j = 0; j < 4; j++) {
            wmma::store_matrix_sync(&cbuf[w][0][0], acc[i][j], CPAD, wmma::mem_row_major);
            __syncwarp();
            int row = rowBlock + wm*32 + i*16 + er;
            int col = colBlock + wn*64 + j*16 + ec;
            size_t obase = (size_t)row * N + col;
#pragma unroll
            for (int c = 0; c < 8; c++) {
                float vv = cbuf[w][er][ec + c];
                if (BIAS) vv += bias[col + c];
                if (RES)  vv += res[obase + c];
                if (RELU) vv = fmaxf(vv, 0.f);
                if (ROUND) vv = wmma::__float_to_tf32(vv);
                C[obase + c] = vv;
            }
            __syncwarp();
        }
    }
}

// ---------------- Flash attention (causal, online softmax) ----------------
// qkv layout: row m = b*S+s, cols [0,1024)=Q, [1024,2048)=K, [2048,3072)=V, col = h*64+e
// grid: (B*H, S/128), block: 128 threads, 1 query per thread.
// Heavy (late-causal) q-tiles scheduled first via reversed mapping.
__global__ __launch_bounds__(128) void attn_kernel(const float* __restrict__ qkv,
                                                   float* __restrict__ ctx)
{
    int bh = blockIdx.x;
    int b  = bh / HH, h = bh % HH;
    int qt = gridDim.y - 1 - blockIdx.y;   // heavy tiles first
    int t  = threadIdx.x;
    int s  = qt * 128 + t;

    const float scale = 0.03125f;   // D^-0.5 = 1/32

    float q[HSZ];
    {
        const float* qrow = qkv + ((size_t)(b*SS + s)) * QKVN + h*HSZ;
#pragma unroll
        for (int e = 0; e < HSZ; e += 4) {
            float4 qv = *(const float4*)(qrow + e);
            q[e+0] = qv.x * scale; q[e+1] = qv.y * scale;
            q[e+2] = qv.z * scale; q[e+3] = qv.w * scale;
        }
    }

    float o[HSZ];
#pragma unroll
    for (int e = 0; e < HSZ; e++) o[e] = 0.f;
    float m = -1e30f, l = 0.f;

    __shared__ float Ks[64][64];
    __shared__ float Vs[64][64];

    int ntiles = 2*qt + 2;
    int r  = t >> 1;
    int c0 = (t & 1) * 32;

    for (int kt = 0; kt < ntiles; kt++) {
        size_t krowbase = ((size_t)(b*SS + kt*64 + r)) * QKVN + h*HSZ + c0;
        const float* krow = qkv + krowbase + DD;
        const float* vrow = qkv + krowbase + 2*DD;
#pragma unroll
        for (int i = 0; i < 8; i++) {
            *(float4*)&Ks[r][c0 + i*4] = ((const float4*)krow)[i];
            *(float4*)&Vs[r][c0 + i*4] = ((const float4*)vrow)[i];
        }
        __syncthreads();

        int jmax = s - kt*64 + 1;
        if (jmax > 64) jmax = 64;
        for (int j = 0; j < jmax; j++) {
            float sv0 = 0.f, sv1 = 0.f, sv2 = 0.f, sv3 = 0.f;
#pragma unroll
            for (int e = 0; e < HSZ; e += 4) {
                sv0 = fmaf(q[e+0], Ks[j][e+0], sv0);
                sv1 = fmaf(q[e+1], Ks[j][e+1], sv1);
                sv2 = fmaf(q[e+2], Ks[j][e+2], sv2);
                sv3 = fmaf(q[e+3], Ks[j][e+3], sv3);
            }
            float sv = (sv0 + sv1) + (sv2 + sv3);
            if (sv <= m) {
                float p = __expf(sv - m);
                l += p;
#pragma unroll
                for (int e = 0; e < HSZ; e++) o[e] = fmaf(p, Vs[j][e], o[e]);
            } else {
                float c = __expf(m - sv);
                m = sv;
                l = l*c + 1.f;
#pragma unroll
                for (int e = 0; e < HSZ; e++) o[e] = fmaf(o[e], c, Vs[j][e]);
            }
        }
        __syncthreads();
    }

    float inv = 1.f / l;
    float* orow = ctx + ((size_t)(b*SS + s)) * DD + h*HSZ;
#pragma unroll
    for (int e = 0; e < HSZ; e += 4) {
        float4 ov;
        ov.x = wmma::__float_to_tf32(o[e+0]*inv);
        ov.y = wmma::__float_to_tf32(o[e+1]*inv);
        ov.z = wmma::__float_to_tf32(o[e+2]*inv);
        ov.w = wmma::__float_to_tf32(o[e+3]*inv);
        *(float4*)(orow + e) = ov;
    }
}

// ---------------- host launcher ----------------
extern "C" void kernel_launch(void* const* d_in, const int* in_sizes, int n_in,
                              void* d_out, int out_size)
{
    const float* x         = (const float*)d_in[0];
    const float* ln1_scale = (const float*)d_in[1];
    const float* ln1_bias  = (const float*)d_in[2];
    const float* Wq        = (const float*)d_in[3];
    const float* Wk        = (const float*)d_in[4];
    const float* Wv        = (const float*)d_in[5];
    const float* Wo        = (const float*)d_in[6];
    const float* bo        = (const float*)d_in[7];
    const float* ln2_scale = (const float*)d_in[8];
    const float* ln2_bias  = (const float*)d_in[9];
    const float* W1        = (const float*)d_in[10];
    const float* b1        = (const float*)d_in[11];
    const float* W2        = (const float*)d_in[12];
    const float* b2        = (const float*)d_in[13];
    float* out = (float*)d_out;

    float *h, *wqkv, *qkv, *ctx, *x1, *h2, *ff, *wo, *w1, *w2;
    cudaGetSymbolAddress((void**)&h,    g_h);
    cudaGetSymbolAddress((void**)&wqkv, g_wqkv);
    cudaGetSymbolAddress((void**)&qkv,  g_qkv);
    cudaGetSymbolAddress((void**)&ctx,  g_ctx);
    cudaGetSymbolAddress((void**)&x1,   g_x1);
    cudaGetSymbolAddress((void**)&h2,   g_h2);
    cudaGetSymbolAddress((void**)&ff,   g_ff);
    cudaGetSymbolAddress((void**)&wo,   g_wo);
    cudaGetSymbolAddress((void**)&w1,   g_w1);
    cudaGetSymbolAddress((void**)&w2,   g_w2);

    // weight prep (tf32 RN)
    repack_qkv<<<(HH*DD*HSZ)/256, 256>>>(Wq, Wk, Wv, wqkv);
    round_tf32_k<<<(DD*DD/4)/256, 256>>>(Wo, wo);
    round_tf32_k<<<(DD*FF/4)/256, 256>>>(W1, w1);
    round_tf32_k<<<(FF*DD/4)/256, 256>>>(W2, w2);

    // LN1 (tf32-rounded out)
    ln_kernel<<<MM, 256>>>(x, ln1_scale, ln1_bias, h);
    // QKV projection: [4096,1024] @ [1024,3072]
    gemm_tf32<false,false,false,false><<<dim3(QKVN/128, MM/128), 256>>>(h, wqkv, nullptr, nullptr, qkv, MM, QKVN, DD);
    // attention (ctx tf32-rounded)
    attn_kernel<<<dim3(BB*HH, SS/128), 128>>>(qkv, ctx);
    // output projection + bias + residual x (fp32 out)
    gemm_tf32<true,true,false,false><<<dim3(DD/128, MM/128), 256>>>(ctx, wo, bo, x, x1, MM, DD, DD);
    // LN2 (tf32-rounded out)
    ln_kernel<<<MM, 256>>>(x1, ln2_scale, ln2_bias, h2);
    // FF1 + relu (tf32-rounded out)
    gemm_tf32<true,false,true,true><<<dim3(FF/128, MM/128), 256>>>(h2, w1, b1, nullptr, ff, MM, FF, DD);
    // FF2 + bias + residual x1 -> out (fp32)
    gemm_tf32<true,true,false,false><<<dim3(DD/128, MM/128), 256>>>(ff, w2, b2, x1, out, MM, DD, FF);
}

// round 4
// speedup vs baseline: 2.3222x; 1.7695x over previous
#include <cuda_runtime.h>
#include <cuda_bf16.h>
#include <mma.h>
#include <math.h>

using namespace nvcuda;

// ---------------- problem constants ----------------
#define BB 2
#define SS 2048
#define DD 1024
#define HH 16
#define HSZ 64
#define FF 4096
#define MM (BB*SS)          // 4096 rows
#define QKVN (3*DD)         // 3072

#define NEG_INF __int_as_float(0xff800000)

// ---------------- scratch (static device globals; no allocation) ----------------
__device__ __nv_bfloat16 g_h   [MM*DD];          // LN1 output
__device__ __nv_bfloat16 g_wqkv[DD*QKVN];        // repacked [D, 3072]
__device__ float         g_qkv [(size_t)MM*QKVN];
__device__ __nv_bfloat16 g_ctx [MM*DD];          // attention out
__device__ float         g_x1  [MM*DD];          // post-attention residual (fp32)
__device__ __nv_bfloat16 g_h2  [MM*DD];          // LN2 output
__device__ __nv_bfloat16 g_ff  [(size_t)MM*FF];  // FF1 out
__device__ __nv_bfloat16 g_wo  [DD*DD];
__device__ __nv_bfloat16 g_w1  [DD*FF];
__device__ __nv_bfloat16 g_w2  [FF*DD];

// ---------------- cp.async helpers ----------------
__device__ __forceinline__ void cp16(void* smem, const void* gmem) {
    unsigned s = (unsigned)__cvta_generic_to_shared(smem);
    asm volatile("cp.async.cg.shared.global [%0], [%1], 16;\n" :: "r"(s), "l"(gmem));
}
#define CP_COMMIT asm volatile("cp.async.commit_group;\n" ::: "memory")
#define CP_WAIT1  asm volatile("cp.async.wait_group 1;\n" ::: "memory")
#define CP_WAIT0  asm volatile("cp.async.wait_group 0;\n" ::: "memory")

// ---------------- LayerNorm: one block per row, 256 threads, bf16 out ----------------
__global__ __launch_bounds__(256) void ln_kernel(const float* __restrict__ in,
                                                 const float* __restrict__ sc,
                                                 const float* __restrict__ bi,
                                                 __nv_bfloat16* __restrict__ out)
{
    int row = blockIdx.x;
    const float* x = in + (size_t)row * DD;
    float v[4];
    float s = 0.f, sq = 0.f;
#pragma unroll
    for (int i = 0; i < 4; i++) {
        v[i] = x[threadIdx.x + i*256];
        s  += v[i];
        sq += v[i]*v[i];
    }
#pragma unroll
    for (int off = 16; off; off >>= 1) {
        s  += __shfl_xor_sync(0xFFFFFFFFu, s,  off);
        sq += __shfl_xor_sync(0xFFFFFFFFu, sq, off);
    }
    __shared__ float ws[8], wq[8];
    int w = threadIdx.x >> 5, ln = threadIdx.x & 31;
    if (ln == 0) { ws[w] = s; wq[w] = sq; }
    __syncthreads();
    s = 0.f; sq = 0.f;
#pragma unroll
    for (int i = 0; i < 8; i++) { s += ws[i]; sq += wq[i]; }
    float mu  = s * (1.f/DD);
    float var = sq * (1.f/DD) - mu*mu;
    float r   = rsqrtf(var + 1e-5f);
    __nv_bfloat16* o = out + (size_t)row * DD;
#pragma unroll
    for (int i = 0; i < 4; i++) {
        int c = threadIdx.x + i*256;
        o[c] = __float2bfloat16_rn((v[i] - mu) * r * sc[c] + bi[c]);
    }
}

// ---------------- repack Wq/Wk/Wv [H,D,HS] -> [D, 3072] bf16 ----------------
__global__ __launch_bounds__(256) void repack_qkv(const float* __restrict__ Wq,
                                                  const float* __restrict__ Wk,
                                                  const float* __restrict__ Wv,
                                                  __nv_bfloat16* __restrict__ Wout)
{
    int idx = blockIdx.x * 256 + threadIdx.x;      // 0 .. 1M-1
    int h   = idx >> 16;
    int rem = idx & 65535;
    int d   = rem >> 6;
    int e   = rem & 63;
    int col = h*HSZ + e;
    size_t base = (size_t)d * QKVN;
    Wout[base          + col] = __float2bfloat16_rn(Wq[idx]);
    Wout[base + DD     + col] = __float2bfloat16_rn(Wk[idx]);
    Wout[base + 2*DD   + col] = __float2bfloat16_rn(Wv[idx]);
}

// ---------------- elementwise fp32 -> bf16 ----------------
__global__ __launch_bounds__(256) void cvt_bf16_k(const float* __restrict__ in,
                                                  __nv_bfloat16* __restrict__ out)
{
    int i = blockIdx.x * 256 + threadIdx.x;
    float4 v = ((const float4*)in)[i];
    __nv_bfloat162 p0 = __floats2bfloat162_rn(v.x, v.y);
    __nv_bfloat162 p1 = __floats2bfloat162_rn(v.z, v.w);
    ((__nv_bfloat162*)out)[2*i]   = p0;
    ((__nv_bfloat162*)out)[2*i+1] = p1;
}

// ---------------- bf16 tensor-core GEMM, cp.async 3-stage ----------------
// C[M,N] = A[M,K] @ B[K,N] (+bias)(+res)(relu)
// 128x128 tile, BK=32, 256 threads (8 warps 4x2), warp tile 32x64, m16n16k16.
#define ALD 40    // As row stride (bf16 elems), mult of 8
#define BLD 136   // Bs row stride
#define CPAD 20
#define AS_ELEMS (128*ALD)
#define BS_ELEMS (32*BLD)
#define GEMM_SMEM (3*AS_ELEMS*2 + 3*BS_ELEMS*2 + 8*16*CPAD*4)

__device__ __forceinline__ void storeC(float* p, float v)         { *p = v; }
__device__ __forceinline__ void storeC(__nv_bfloat16* p, float v) { *p = __float2bfloat16_rn(v); }

template<bool BIAS, bool RES, bool RELU, typename OutT>
__global__ __launch_bounds__(256) void gemm_bf16(const __nv_bfloat16* __restrict__ A,
                                                 const __nv_bfloat16* __restrict__ B,
                                                 const float* __restrict__ bias,
                                                 const float* __restrict__ res,
                                                 OutT* __restrict__ C,
                                                 int M, int N, int K)
{
    extern __shared__ char smem_raw[];
    __nv_bfloat16* As = (__nv_bfloat16*)smem_raw;                               // [3][128][ALD]
    __nv_bfloat16* Bs = (__nv_bfloat16*)(smem_raw + 3*AS_ELEMS*2);              // [3][32][BLD]
    float*       cbuf = (float*)(smem_raw + 3*AS_ELEMS*2 + 3*BS_ELEMS*2);       // [8][16][CPAD]

    int tid  = threadIdx.x;
    int w    = tid >> 5;
    int lane = tid & 31;
    int wm   = w & 3;          // 0..3: 32-row slice
    int wn   = w >> 2;         // 0..1: 64-col slice
    int rowBlock = blockIdx.y * 128;
    int colBlock = blockIdx.x * 128;

    const __nv_bfloat16* Ag = A + (size_t)rowBlock * K;
    const __nv_bfloat16* Bg = B + colBlock;

    // per-thread load coords: A tile 128x32 (4 chunks/row), B tile 32x128 (16 chunks/row)
    int a_r = tid >> 1,  a_c = (tid & 1) * 16;   // two 16B chunks: a_c, a_c+8
    int b_r = tid >> 3,  b_c = (tid & 7) * 16;

    wmma::fragment<wmma::accumulator, 16, 16, 16, float> acc[2][4];
#pragma unroll
    for (int i = 0; i < 2; i++)
#pragma unroll
        for (int j = 0; j < 4; j++) wmma::fill_fragment(acc[i][j], 0.f);

    auto prefetch = [&](int st, int kb) {
        __nv_bfloat16* as = As + (size_t)st * AS_ELEMS;
        __nv_bfloat16* bs = Bs + (size_t)st * BS_ELEMS;
        cp16(as + a_r*ALD + a_c,     Ag + (size_t)a_r * K + kb + a_c);
        cp16(as + a_r*ALD + a_c + 8, Ag + (size_t)a_r * K + kb + a_c + 8);
        cp16(bs + b_r*BLD + b_c,     Bg + (size_t)(kb + b_r) * N + b_c);
        cp16(bs + b_r*BLD + b_c + 8, Bg + (size_t)(kb + b_r) * N + b_c + 8);
        CP_COMMIT;
    };

    prefetch(0, 0);
    prefetch(1, 32);

    int nIter = K >> 5;
    for (int kt = 0; kt < nIter; kt++) {
        if (kt == nIter - 1) { CP_WAIT0; } else { CP_WAIT1; }
        __syncthreads();
        if (kt + 2 < nIter) prefetch((kt + 2) % 3, (kt + 2) << 5);

        int buf = kt % 3;
        const __nv_bfloat16* as = As + (size_t)buf * AS_ELEMS;
        const __nv_bfloat16* bs = Bs + (size_t)buf * BS_ELEMS;
#pragma unroll
        for (int ks = 0; ks < 2; ks++) {
            wmma::fragment<wmma::matrix_a, 16, 16, 16, __nv_bfloat16, wmma::row_major> af[2];
            wmma::fragment<wmma::matrix_b, 16, 16, 16, __nv_bfloat16, wmma::row_major> bf[4];
#pragma unroll
            for (int i = 0; i < 2; i++)
                wmma::load_matrix_sync(af[i], as + (wm*32 + i*16)*ALD + ks*16, ALD);
#pragma unroll
            for (int j = 0; j < 4; j++)
                wmma::load_matrix_sync(bf[j], bs + (ks*16)*BLD + wn*64 + j*16, BLD);
#pragma unroll
            for (int i = 0; i < 2; i++)
#pragma unroll
                for (int j = 0; j < 4; j++)
                    wmma::mma_sync(acc[i][j], af[i], bf[j], acc[i][j]);
        }
        __syncthreads();
    }

    // epilogue: stage each 16x16 frag through smem, apply postops
    float* cb = cbuf + w * 16 * CPAD;
    int er = lane >> 1;          // 0..15
    int ec = (lane & 1) * 8;     // 0 or 8
#pragma unroll
    for (int i = 0; i < 2; i++) {
#pragma unroll
        for (int j = 0; j < 4; j++) {
            wmma::store_matrix_sync(cb, acc[i][j], CPAD, wmma::mem_row_major);
            __syncwarp();
            int row = rowBlock + wm*32 + i*16 + er;
            int col = colBlock + wn*64 + j*16 + ec;
            size_t obase = (size_t)row * N + col;
#pragma unroll
            for (int c = 0; c < 8; c++) {
                float vv = cb[er*CPAD + ec + c];
                if (BIAS) vv += bias[col + c];
                if (RES)  vv += res[obase + c];
                if (RELU) vv = fmaxf(vv, 0.f);
                storeC(&C[obase + c], vv);
            }
            __syncwarp();
        }
    }
}

// ---------------- Flash attention (causal, chunked online softmax) ----------------
// qkv layout: row m = b*S+s, cols [0,1024)=Q, [1024,2048)=K, [2048,3072)=V, col = h*64+e
// grid: (B*H, S/128), block: 128 threads, 1 query per thread, 16-key chunks.
__global__ __launch_bounds__(128) void attn_kernel(const float* __restrict__ qkv,
                                                   __nv_bfloat16* __restrict__ ctx)
{
    int bh = blockIdx.x;
    int b  = bh / HH, h = bh % HH;
    int qt = gridDim.y - 1 - blockIdx.y;   // heavy tiles first
    int t  = threadIdx.x;
    int s  = qt * 128 + t;

    const float scale = 0.03125f;   // D^-0.5 = 1/32

    float q[HSZ];
    {
        const float* qrow = qkv + ((size_t)(b*SS + s)) * QKVN + h*HSZ;
#pragma unroll
        for (int e = 0; e < HSZ; e += 4) {
            float4 qv = *(const float4*)(qrow + e);
            q[e+0] = qv.x * scale; q[e+1] = qv.y * scale;
            q[e+2] = qv.z * scale; q[e+3] = qv.w * scale;
        }
    }

    float o[HSZ];
#pragma unroll
    for (int e = 0; e < HSZ; e++) o[e] = 0.f;
    float m = -1e30f, l = 0.f;

    __shared__ float Ks[64][68];
    __shared__ float Vs[64][68];

    int ntiles = 2*qt + 2;
    int r  = t >> 1;
    int c0 = (t & 1) * 32;

    for (int kt = 0; kt < ntiles; kt++) {
        size_t krowbase = ((size_t)(b*SS + kt*64 + r)) * QKVN + h*HSZ + c0;
        const float* krow = qkv + krowbase + DD;
        const float* vrow = qkv + krowbase + 2*DD;
#pragma unroll
        for (int i = 0; i < 8; i++) {
            *(float4*)&Ks[r][c0 + i*4] = ((const float4*)krow)[i];
            *(float4*)&Vs[r][c0 + i*4] = ((const float4*)vrow)[i];
        }
        __syncthreads();

        int jmax = s - kt*64 + 1;           // may be <=0 (thread idle this tile)
        if (jmax > 64) jmax = 64;

        for (int j0 = 0; j0 < jmax; j0 += 16) {
            float sc[16];
#pragma unroll
            for (int jj = 0; jj < 16; jj++) {
                int j = j0 + jj;
                float d0 = 0.f, d1 = 0.f, d2 = 0.f, d3 = 0.f;
#pragma unroll
                for (int e = 0; e < HSZ; e += 4) {
                    d0 = fmaf(q[e+0], Ks[j][e+0], d0);
                    d1 = fmaf(q[e+1], Ks[j][e+1], d1);
                    d2 = fmaf(q[e+2], Ks[j][e+2], d2);
                    d3 = fmaf(q[e+3], Ks[j][e+3], d3);
                }
                sc[jj] = (j < jmax) ? (d0 + d1) + (d2 + d3) : NEG_INF;
            }
            float cm = sc[0];
#pragma unroll
            for (int jj = 1; jj < 16; jj++) cm = fmaxf(cm, sc[jj]);
            if (cm > m) {
                float corr = __expf(m - cm);
                m = cm;
                l *= corr;
#pragma unroll
                for (int e = 0; e < HSZ; e++) o[e] *= corr;
            }
#pragma unroll
            for (int jj = 0; jj < 16; jj++) {
                float p = __expf(sc[jj] - m);
                l += p;
#pragma unroll
                for (int e = 0; e < HSZ; e++)
                    o[e] = fmaf(p, Vs[j0 + jj][e], o[e]);
            }
        }
        __syncthreads();
    }

    float inv = 1.f / l;
    __nv_bfloat16* orow = ctx + ((size_t)(b*SS + s)) * DD + h*HSZ;
#pragma unroll
    for (int e = 0; e < HSZ; e += 2) {
        *(__nv_bfloat162*)(orow + e) = __floats2bfloat162_rn(o[e]*inv, o[e+1]*inv);
    }
}

// ---------------- host launcher ----------------
extern "C" void kernel_launch(void* const* d_in, const int* in_sizes, int n_in,
                              void* d_out, int out_size)
{
    const float* x         = (const float*)d_in[0];
    const float* ln1_scale = (const float*)d_in[1];
    const float* ln1_bias  = (const float*)d_in[2];
    const float* Wq        = (const float*)d_in[3];
    const float* Wk        = (const float*)d_in[4];
    const float* Wv        = (const float*)d_in[5];
    const float* Wo        = (const float*)d_in[6];
    const float* bo        = (const float*)d_in[7];
    const float* ln2_scale = (const float*)d_in[8];
    const float* ln2_bias  = (const float*)d_in[9];
    const float* W1        = (const float*)d_in[10];
    const float* b1        = (const float*)d_in[11];
    const float* W2        = (const float*)d_in[12];
    const float* b2        = (const float*)d_in[13];
    float* out = (float*)d_out;

    __nv_bfloat16 *h, *wqkv, *ctx, *h2, *ff, *wo, *w1, *w2;
    float *qkv, *x1;
    cudaGetSymbolAddress((void**)&h,    g_h);
    cudaGetSymbolAddress((void**)&wqkv, g_wqkv);
    cudaGetSymbolAddress((void**)&qkv,  g_qkv);
    cudaGetSymbolAddress((void**)&ctx,  g_ctx);
    cudaGetSymbolAddress((void**)&x1,   g_x1);
    cudaGetSymbolAddress((void**)&h2,   g_h2);
    cudaGetSymbolAddress((void**)&ff,   g_ff);
    cudaGetSymbolAddress((void**)&wo,   g_wo);
    cudaGetSymbolAddress((void**)&w1,   g_w1);
    cudaGetSymbolAddress((void**)&w2,   g_w2);

    // enable >48KB dynamic smem on the 4 GEMM instantiations (idempotent)
    cudaFuncSetAttribute(gemm_bf16<false,false,false,float>,
                         cudaFuncAttributeMaxDynamicSharedMemorySize, GEMM_SMEM);
    cudaFuncSetAttribute(gemm_bf16<true,true,false,float>,
                         cudaFuncAttributeMaxDynamicSharedMemorySize, GEMM_SMEM);
    cudaFuncSetAttribute(gemm_bf16<true,false,true,__nv_bfloat16>,
                         cudaFuncAttributeMaxDynamicSharedMemorySize, GEMM_SMEM);

    // weight prep (bf16)
    repack_qkv<<<(HH*DD*HSZ)/256, 256>>>(Wq, Wk, Wv, wqkv);
    cvt_bf16_k<<<(DD*DD/4)/256, 256>>>(Wo, wo);
    cvt_bf16_k<<<(DD*FF/4)/256, 256>>>(W1, w1);
    cvt_bf16_k<<<(FF*DD/4)/256, 256>>>(W2, w2);

    // LN1 (bf16 out)
    ln_kernel<<<MM, 256>>>(x, ln1_scale, ln1_bias, h);
    // QKV projection: [4096,1024] @ [1024,3072] -> fp32
    gemm_bf16<false,false,false,float><<<dim3(QKVN/128, MM/128), 256, GEMM_SMEM>>>(h, wqkv, nullptr, nullptr, qkv, MM, QKVN, DD);
    // attention (ctx bf16)
    attn_kernel<<<dim3(BB*HH, SS/128), 128>>>(qkv, ctx);
    // output projection + bias + residual x -> x1 (fp32)
    gemm_bf16<true,true,false,float><<<dim3(DD/128, MM/128), 256, GEMM_SMEM>>>(ctx, wo, bo, x, x1, MM, DD, DD);
    // LN2 (bf16 out)
    ln_kernel<<<MM, 256>>>(x1, ln2_scale, ln2_bias, h2);
    // FF1 + relu (bf16 out)
    gemm_bf16<true,false,true,__nv_bfloat16><<<dim3(FF/128, MM/128), 256, GEMM_SMEM>>>(h2, w1, b1, nullptr, ff, MM, FF, DD);
    // FF2 + bias + residual x1 -> out (fp32)
    gemm_bf16<true,true,false,float><<<dim3(DD/128, MM/128), 256, GEMM_SMEM>>>(ff, w2, b2, x1, out, MM, DD, FF);
}

// round 5
// speedup vs baseline: 4.1346x; 1.7805x over previous
#include <cuda_runtime.h>
#include <cuda_bf16.h>
#include <mma.h>
#include <math.h>

using namespace nvcuda;

// ---------------- problem constants ----------------
#define BB 2
#define SS 2048
#define DD 1024
#define HH 16
#define HSZ 64
#define FF 4096
#define MM (BB*SS)          // 4096 rows
#define QKVN (3*DD)         // 3072

#define MNEG  (-1e30f)

// ---------------- scratch (static device globals; no allocation) ----------------
__device__ __nv_bfloat16 g_h   [MM*DD];          // LN1 output
__device__ __nv_bfloat16 g_wqkv[DD*QKVN];        // repacked [D, 3072] (Wq pre-scaled by 1/32)
__device__ __nv_bfloat16 g_qkvh[(size_t)MM*QKVN];// QKV bf16
__device__ __nv_bfloat16 g_ctx [MM*DD];          // attention out
__device__ float         g_x1  [MM*DD];          // post-attention residual (fp32)
__device__ __nv_bfloat16 g_h2  [MM*DD];          // LN2 output
__device__ __nv_bfloat16 g_ff  [(size_t)MM*FF];  // FF1 out
__device__ __nv_bfloat16 g_wo  [DD*DD];
__device__ __nv_bfloat16 g_w1  [DD*FF];
__device__ __nv_bfloat16 g_w2  [FF*DD];

// ---------------- cp.async helpers ----------------
__device__ __forceinline__ void cp16(void* smem, const void* gmem) {
    unsigned s = (unsigned)__cvta_generic_to_shared(smem);
    asm volatile("cp.async.cg.shared.global [%0], [%1], 16;\n" :: "r"(s), "l"(gmem));
}
#define CP_COMMIT asm volatile("cp.async.commit_group;\n" ::: "memory")
#define CP_WAIT1  asm volatile("cp.async.wait_group 1;\n" ::: "memory")
#define CP_WAIT0  asm volatile("cp.async.wait_group 0;\n" ::: "memory")

// ---------------- mma / ldmatrix primitives ----------------
__device__ __forceinline__ unsigned smem_u32(const void* p) {
    return (unsigned)__cvta_generic_to_shared(p);
}
__device__ __forceinline__ void ldmx2(unsigned a, unsigned &r0, unsigned &r1) {
    asm volatile("ldmatrix.sync.aligned.m8n8.x2.shared.b16 {%0,%1}, [%2];"
                 : "=r"(r0), "=r"(r1) : "r"(a));
}
__device__ __forceinline__ void ldmx2t(unsigned a, unsigned &r0, unsigned &r1) {
    asm volatile("ldmatrix.sync.aligned.m8n8.x2.trans.shared.b16 {%0,%1}, [%2];"
                 : "=r"(r0), "=r"(r1) : "r"(a));
}
__device__ __forceinline__ void ldmx4(unsigned a, unsigned &r0, unsigned &r1, unsigned &r2, unsigned &r3) {
    asm volatile("ldmatrix.sync.aligned.m8n8.x4.shared.b16 {%0,%1,%2,%3}, [%4];"
                 : "=r"(r0), "=r"(r1), "=r"(r2), "=r"(r3) : "r"(a));
}
__device__ __forceinline__ void mma_bf16(float* c, const unsigned* a, unsigned b0, unsigned b1) {
    asm volatile("mma.sync.aligned.m16n8k16.row.col.f32.bf16.bf16.f32 "
                 "{%0,%1,%2,%3}, {%4,%5,%6,%7}, {%8,%9}, {%0,%1,%2,%3};"
                 : "+f"(c[0]), "+f"(c[1]), "+f"(c[2]), "+f"(c[3])
                 : "r"(a[0]), "r"(a[1]), "r"(a[2]), "r"(a[3]), "r"(b0), "r"(b1));
}
__device__ __forceinline__ unsigned pk_bf2(float x, float y) {
    __nv_bfloat162 v = __floats2bfloat162_rn(x, y);
    return *(unsigned*)&v;
}

// ---------------- LayerNorm: one block per row, 256 threads, bf16 out ----------------
__global__ __launch_bounds__(256) void ln_kernel(const float* __restrict__ in,
                                                 const float* __restrict__ sc,
                                                 const float* __restrict__ bi,
                                                 __nv_bfloat16* __restrict__ out)
{
    int row = blockIdx.x;
    const float* x = in + (size_t)row * DD;
    float v[4];
    float s = 0.f, sq = 0.f;
#pragma unroll
    for (int i = 0; i < 4; i++) {
        v[i] = x[threadIdx.x + i*256];
        s  += v[i];
        sq += v[i]*v[i];
    }
#pragma unroll
    for (int off = 16; off; off >>= 1) {
        s  += __shfl_xor_sync(0xFFFFFFFFu, s,  off);
        sq += __shfl_xor_sync(0xFFFFFFFFu, sq, off);
    }
    __shared__ float ws[8], wq[8];
    int w = threadIdx.x >> 5, ln = threadIdx.x & 31;
    if (ln == 0) { ws[w] = s; wq[w] = sq; }
    __syncthreads();
    s = 0.f; sq = 0.f;
#pragma unroll
    for (int i = 0; i < 8; i++) { s += ws[i]; sq += wq[i]; }
    float mu  = s * (1.f/DD);
    float var = sq * (1.f/DD) - mu*mu;
    float r   = rsqrtf(var + 1e-5f);
    __nv_bfloat16* o = out + (size_t)row * DD;
#pragma unroll
    for (int i = 0; i < 4; i++) {
        int c = threadIdx.x + i*256;
        o[c] = __float2bfloat16_rn((v[i] - mu) * r * sc[c] + bi[c]);
    }
}

// ---------------- repack Wq/Wk/Wv [H,D,HS] -> [D, 3072] bf16; Wq scaled by 1/32 ----------------
__global__ __launch_bounds__(256) void repack_qkv(const float* __restrict__ Wq,
                                                  const float* __restrict__ Wk,
                                                  const float* __restrict__ Wv,
                                                  __nv_bfloat16* __restrict__ Wout)
{
    int idx = blockIdx.x * 256 + threadIdx.x;      // 0 .. 1M-1
    int h   = idx >> 16;
    int rem = idx & 65535;
    int d   = rem >> 6;
    int e   = rem & 63;
    int col = h*HSZ + e;
    size_t base = (size_t)d * QKVN;
    Wout[base          + col] = __float2bfloat16_rn(Wq[idx] * 0.03125f);  // fold D^-0.5
    Wout[base + DD     + col] = __float2bfloat16_rn(Wk[idx]);
    Wout[base + 2*DD   + col] = __float2bfloat16_rn(Wv[idx]);
}

// ---------------- elementwise fp32 -> bf16 ----------------
__global__ __launch_bounds__(256) void cvt_bf16_k(const float* __restrict__ in,
                                                  __nv_bfloat16* __restrict__ out)
{
    int i = blockIdx.x * 256 + threadIdx.x;
    float4 v = ((const float4*)in)[i];
    ((__nv_bfloat162*)out)[2*i]   = __floats2bfloat162_rn(v.x, v.y);
    ((__nv_bfloat162*)out)[2*i+1] = __floats2bfloat162_rn(v.z, v.w);
}

// ---------------- bf16 tensor-core GEMM, cp.async 3-stage ----------------
#define ALD 40
#define BLD 136
#define CPAD 20
#define AS_ELEMS (128*ALD)
#define BS_ELEMS (32*BLD)
#define GEMM_SMEM (3*AS_ELEMS*2 + 3*BS_ELEMS*2 + 8*16*CPAD*4)

__device__ __forceinline__ void storeC(float* p, float v)         { *p = v; }
__device__ __forceinline__ void storeC(__nv_bfloat16* p, float v) { *p = __float2bfloat16_rn(v); }

template<bool BIAS, bool RES, bool RELU, typename OutT>
__global__ __launch_bounds__(256) void gemm_bf16(const __nv_bfloat16* __restrict__ A,
                                                 const __nv_bfloat16* __restrict__ B,
                                                 const float* __restrict__ bias,
                                                 const float* __restrict__ res,
                                                 OutT* __restrict__ C,
                                                 int M, int N, int K)
{
    extern __shared__ char smem_raw[];
    __nv_bfloat16* As = (__nv_bfloat16*)smem_raw;
    __nv_bfloat16* Bs = (__nv_bfloat16*)(smem_raw + 3*AS_ELEMS*2);
    float*       cbuf = (float*)(smem_raw + 3*AS_ELEMS*2 + 3*BS_ELEMS*2);

    int tid  = threadIdx.x;
    int w    = tid >> 5;
    int lane = tid & 31;
    int wm   = w & 3;
    int wn   = w >> 2;
    int rowBlock = blockIdx.y * 128;
    int colBlock = blockIdx.x * 128;

    const __nv_bfloat16* Ag = A + (size_t)rowBlock * K;
    const __nv_bfloat16* Bg = B + colBlock;

    int a_r = tid >> 1,  a_c = (tid & 1) * 16;
    int b_r = tid >> 3,  b_c = (tid & 7) * 16;

    wmma::fragment<wmma::accumulator, 16, 16, 16, float> acc[2][4];
#pragma unroll
    for (int i = 0; i < 2; i++)
#pragma unroll
        for (int j = 0; j < 4; j++) wmma::fill_fragment(acc[i][j], 0.f);

    auto prefetch = [&](int st, int kb) {
        __nv_bfloat16* as = As + (size_t)st * AS_ELEMS;
        __nv_bfloat16* bs = Bs + (size_t)st * BS_ELEMS;
        cp16(as + a_r*ALD + a_c,     Ag + (size_t)a_r * K + kb + a_c);
        cp16(as + a_r*ALD + a_c + 8, Ag + (size_t)a_r * K + kb + a_c + 8);
        cp16(bs + b_r*BLD + b_c,     Bg + (size_t)(kb + b_r) * N + b_c);
        cp16(bs + b_r*BLD + b_c + 8, Bg + (size_t)(kb + b_r) * N + b_c + 8);
        CP_COMMIT;
    };

    prefetch(0, 0);
    prefetch(1, 32);

    int nIter = K >> 5;
    for (int kt = 0; kt < nIter; kt++) {
        if (kt == nIter - 1) { CP_WAIT0; } else { CP_WAIT1; }
        __syncthreads();
        if (kt + 2 < nIter) prefetch((kt + 2) % 3, (kt + 2) << 5);

        int buf = kt % 3;
        const __nv_bfloat16* as = As + (size_t)buf * AS_ELEMS;
        const __nv_bfloat16* bs = Bs + (size_t)buf * BS_ELEMS;
#pragma unroll
        for (int ks = 0; ks < 2; ks++) {
            wmma::fragment<wmma::matrix_a, 16, 16, 16, __nv_bfloat16, wmma::row_major> af[2];
            wmma::fragment<wmma::matrix_b, 16, 16, 16, __nv_bfloat16, wmma::row_major> bf[4];
#pragma unroll
            for (int i = 0; i < 2; i++)
                wmma::load_matrix_sync(af[i], as + (wm*32 + i*16)*ALD + ks*16, ALD);
#pragma unroll
            for (int j = 0; j < 4; j++)
                wmma::load_matrix_sync(bf[j], bs + (ks*16)*BLD + wn*64 + j*16, BLD);
#pragma unroll
            for (int i = 0; i < 2; i++)
#pragma unroll
                for (int j = 0; j < 4; j++)
                    wmma::mma_sync(acc[i][j], af[i], bf[j], acc[i][j]);
        }
        __syncthreads();
    }

    float* cb = cbuf + w * 16 * CPAD;
    int er = lane >> 1;
    int ec = (lane & 1) * 8;
#pragma unroll
    for (int i = 0; i < 2; i++) {
#pragma unroll
        for (int j = 0; j < 4; j++) {
            wmma::store_matrix_sync(cb, acc[i][j], CPAD, wmma::mem_row_major);
            __syncwarp();
            int row = rowBlock + wm*32 + i*16 + er;
            int col = colBlock + wn*64 + j*16 + ec;
            size_t obase = (size_t)row * N + col;
#pragma unroll
            for (int c = 0; c < 8; c++) {
                float vv = cb[er*CPAD + ec + c];
                if (BIAS) vv += bias[col + c];
                if (RES)  vv += res[obase + c];
                if (RELU) vv = fmaxf(vv, 0.f);
                storeC(&C[obase + c], vv);
            }
            __syncwarp();
        }
    }
}

// ---------------- Tensor-core flash attention (causal) ----------------
// Br=64 rows/block (4 warps x 16 rows), Bc=64 keys/tile. qkv bf16, Q pre-scaled.
#define AP 72   // smem pitch (bf16 elems) = 144B -> conflict-free ldmatrix

__global__ __launch_bounds__(128) void attn_mma(const __nv_bfloat16* __restrict__ qkv,
                                                __nv_bfloat16* __restrict__ ctx)
{
    __shared__ __nv_bfloat16 Qs[64][AP];
    __shared__ __nv_bfloat16 Ks[2][64][AP];
    __shared__ __nv_bfloat16 Vs[2][64][AP];

    int bh = blockIdx.x;
    int b = bh >> 4, h = bh & 15;
    int qt = (int)gridDim.y - 1 - (int)blockIdx.y;   // heavy tiles first
    int tid = threadIdx.x;
    int w = tid >> 5, lane = tid & 31;
    int g = lane >> 2, t = lane & 3;

    const __nv_bfloat16* base = qkv + (size_t)(b*SS) * QKVN + h*HSZ;
    int ntiles = qt + 1;

    int lr = tid >> 3, lc = (tid & 7) * 8;   // loader coords: row lr(+16i), 16B chunk lc

    // Q tile (group 0)
#pragma unroll
    for (int i = 0; i < 4; i++) {
        int rr = lr + i*16;
        cp16(&Qs[rr][lc], base + (size_t)(64*qt + rr) * QKVN + lc);
    }
    CP_COMMIT;

    auto loadKV = [&](int st, int kt) {
        const __nv_bfloat16* kb = base + DD     + (size_t)(64*kt) * QKVN;
        const __nv_bfloat16* vb = base + 2*DD   + (size_t)(64*kt) * QKVN;
#pragma unroll
        for (int i = 0; i < 4; i++) {
            int rr = lr + i*16;
            cp16(&Ks[st][rr][lc], kb + (size_t)rr * QKVN + lc);
            cp16(&Vs[st][rr][lc], vb + (size_t)rr * QKVN + lc);
        }
        CP_COMMIT;
    };

    loadKV(0, 0);
    if (ntiles > 1) loadKV(1, 1);
    if (ntiles > 1) { CP_WAIT1; } else { CP_WAIT0; }
    __syncthreads();

    // Q fragments: 4 k-chunks, A-layout (m16n8k16)
    unsigned qf[4][4];
    {
        int qrow = w*16 + (lane & 7) + ((lane >> 3) & 1) * 8;
        int qcol = (lane >> 4) * 8;
#pragma unroll
        for (int kc = 0; kc < 4; kc++)
            ldmx4(smem_u32(&Qs[qrow][kc*16 + qcol]), qf[kc][0], qf[kc][1], qf[kc][2], qf[kc][3]);
    }

    float O[8][4];
#pragma unroll
    for (int j = 0; j < 8; j++)
#pragma unroll
        for (int e = 0; e < 4; e++) O[j][e] = 0.f;
    float m_lo = MNEG, m_hi = MNEG, l_lo = 0.f, l_hi = 0.f;

    for (int kt = 0; kt < ntiles; kt++) {
        int st = kt & 1;

        // ---- S = Q @ K^T (16x64 per warp) ----
        float S[8][4];
#pragma unroll
        for (int j = 0; j < 8; j++)
#pragma unroll
            for (int e = 0; e < 4; e++) S[j][e] = 0.f;

        int l15 = lane & 15;
#pragma unroll
        for (int j = 0; j < 8; j++) {
#pragma unroll
            for (int kc = 0; kc < 4; kc++) {
                unsigned b0, b1;
                int krow = 8*j + (l15 & 7);
                int kcol = kc*16 + ((l15 >> 3) & 1) * 8;
                ldmx2(smem_u32(&Ks[st][krow][kcol]), b0, b1);
                mma_bf16(S[j], qf[kc], b0, b1);
            }
        }

        // ---- causal mask (only the diagonal tile) ----
        if (kt == qt) {
            int lim_lo = w*16 + g;       // row - 64*kt
            int lim_hi = lim_lo + 8;
#pragma unroll
            for (int j = 0; j < 8; j++) {
                int c0 = 8*j + 2*t;
                if (c0     > lim_lo) S[j][0] = MNEG;
                if (c0 + 1 > lim_lo) S[j][1] = MNEG;
                if (c0     > lim_hi) S[j][2] = MNEG;
                if (c0 + 1 > lim_hi) S[j][3] = MNEG;
            }
        }

        // ---- online softmax ----
        float mx_lo = MNEG, mx_hi = MNEG;
#pragma unroll
        for (int j = 0; j < 8; j++) {
            mx_lo = fmaxf(mx_lo, fmaxf(S[j][0], S[j][1]));
            mx_hi = fmaxf(mx_hi, fmaxf(S[j][2], S[j][3]));
        }
        mx_lo = fmaxf(mx_lo, __shfl_xor_sync(0xFFFFFFFFu, mx_lo, 1));
        mx_lo = fmaxf(mx_lo, __shfl_xor_sync(0xFFFFFFFFu, mx_lo, 2));
        mx_hi = fmaxf(mx_hi, __shfl_xor_sync(0xFFFFFFFFu, mx_hi, 1));
        mx_hi = fmaxf(mx_hi, __shfl_xor_sync(0xFFFFFFFFu, mx_hi, 2));

        float nm_lo = fmaxf(m_lo, mx_lo);
        float nm_hi = fmaxf(m_hi, mx_hi);
        float corr_lo = __expf(m_lo - nm_lo);
        float corr_hi = __expf(m_hi - nm_hi);
        m_lo = nm_lo; m_hi = nm_hi;

        float sum_lo = 0.f, sum_hi = 0.f;
        unsigned pf[4][4];
#pragma unroll
        for (int kc = 0; kc < 4; kc++) {
            int j0 = 2*kc, j1 = 2*kc + 1;
            float p00 = __expf(S[j0][0] - m_lo), p01 = __expf(S[j0][1] - m_lo);
            float p02 = __expf(S[j0][2] - m_hi), p03 = __expf(S[j0][3] - m_hi);
            float p10 = __expf(S[j1][0] - m_lo), p11 = __expf(S[j1][1] - m_lo);
            float p12 = __expf(S[j1][2] - m_hi), p13 = __expf(S[j1][3] - m_hi);
            sum_lo += (p00 + p01) + (p10 + p11);
            sum_hi += (p02 + p03) + (p12 + p13);
            pf[kc][0] = pk_bf2(p00, p01);
            pf[kc][1] = pk_bf2(p02, p03);
            pf[kc][2] = pk_bf2(p10, p11);
            pf[kc][3] = pk_bf2(p12, p13);
        }
        sum_lo += __shfl_xor_sync(0xFFFFFFFFu, sum_lo, 1);
        sum_lo += __shfl_xor_sync(0xFFFFFFFFu, sum_lo, 2);
        sum_hi += __shfl_xor_sync(0xFFFFFFFFu, sum_hi, 1);
        sum_hi += __shfl_xor_sync(0xFFFFFFFFu, sum_hi, 2);
        l_lo = l_lo * corr_lo + sum_lo;
        l_hi = l_hi * corr_hi + sum_hi;

#pragma unroll
        for (int j = 0; j < 8; j++) {
            O[j][0] *= corr_lo; O[j][1] *= corr_lo;
            O[j][2] *= corr_hi; O[j][3] *= corr_hi;
        }

        // ---- O += P @ V ----
#pragma unroll
        for (int j = 0; j < 8; j++) {
#pragma unroll
            for (int kc = 0; kc < 4; kc++) {
                unsigned b0, b1;
                int vrow = 16*kc + ((l15 >> 3) & 1) * 8 + (l15 & 7);
                ldmx2t(smem_u32(&Vs[st][vrow][8*j]), b0, b1);
                mma_bf16(O[j], pf[kc], b0, b1);
            }
        }

        __syncthreads();                       // everyone done with stage st
        if (kt + 2 < ntiles) loadKV(st, kt + 2);
        if (kt + 1 < ntiles) {
            if (kt + 2 < ntiles) { CP_WAIT1; } else { CP_WAIT0; }
            __syncthreads();                   // stage (kt+1)&1 ready
        }
    }

    // ---- epilogue ----
    float il_lo = 1.f / l_lo, il_hi = 1.f / l_hi;
    __nv_bfloat16* obase = ctx + (size_t)(b*SS + 64*qt + w*16) * DD + h*HSZ;
#pragma unroll
    for (int j = 0; j < 8; j++) {
        int col = 8*j + 2*t;
        *(__nv_bfloat162*)(obase + (size_t)g       * DD + col) = __floats2bfloat162_rn(O[j][0]*il_lo, O[j][1]*il_lo);
        *(__nv_bfloat162*)(obase + (size_t)(g + 8) * DD + col) = __floats2bfloat162_rn(O[j][2]*il_hi, O[j][3]*il_hi);
    }
}

// ---------------- host launcher ----------------
extern "C" void kernel_launch(void* const* d_in, const int* in_sizes, int n_in,
                              void* d_out, int out_size)
{
    const float* x         = (const float*)d_in[0];
    const float* ln1_scale = (const float*)d_in[1];
    const float* ln1_bias  = (const float*)d_in[2];
    const float* Wq        = (const float*)d_in[3];
    const float* Wk        = (const float*)d_in[4];
    const float* Wv        = (const float*)d_in[5];
    const float* Wo        = (const float*)d_in[6];
    const float* bo        = (const float*)d_in[7];
    const float* ln2_scale = (const float*)d_in[8];
    const float* ln2_bias  = (const float*)d_in[9];
    const float* W1        = (const float*)d_in[10];
    const float* b1        = (const float*)d_in[11];
    const float* W2        = (const float*)d_in[12];
    const float* b2        = (const float*)d_in[13];
    float* out = (float*)d_out;

    __nv_bfloat16 *h, *wqkv, *qkvh, *ctx, *h2, *ff, *wo, *w1, *w2;
    float *x1;
    cudaGetSymbolAddress((void**)&h,    g_h);
    cudaGetSymbolAddress((void**)&wqkv, g_wqkv);
    cudaGetSymbolAddress((void**)&qkvh, g_qkvh);
    cudaGetSymbolAddress((void**)&ctx,  g_ctx);
    cudaGetSymbolAddress((void**)&x1,   g_x1);
    cudaGetSymbolAddress((void**)&h2,   g_h2);
    cudaGetSymbolAddress((void**)&ff,   g_ff);
    cudaGetSymbolAddress((void**)&wo,   g_wo);
    cudaGetSymbolAddress((void**)&w1,   g_w1);
    cudaGetSymbolAddress((void**)&w2,   g_w2);

    cudaFuncSetAttribute(gemm_bf16<false,false,false,__nv_bfloat16>,
                         cudaFuncAttributeMaxDynamicSharedMemorySize, GEMM_SMEM);
    cudaFuncSetAttribute(gemm_bf16<true,true,false,float>,
                         cudaFuncAttributeMaxDynamicSharedMemorySize, GEMM_SMEM);
    cudaFuncSetAttribute(gemm_bf16<true,false,true,__nv_bfloat16>,
                         cudaFuncAttributeMaxDynamicSharedMemorySize, GEMM_SMEM);

    // weight prep (bf16)
    repack_qkv<<<(HH*DD*HSZ)/256, 256>>>(Wq, Wk, Wv, wqkv);
    cvt_bf16_k<<<(DD*DD/4)/256, 256>>>(Wo, wo);
    cvt_bf16_k<<<(DD*FF/4)/256, 256>>>(W1, w1);
    cvt_bf16_k<<<(FF*DD/4)/256, 256>>>(W2, w2);

    // LN1 (bf16 out)
    ln_kernel<<<MM, 256>>>(x, ln1_scale, ln1_bias, h);
    // QKV projection -> bf16 (Q pre-scaled via Wq)
    gemm_bf16<false,false,false,__nv_bfloat16><<<dim3(QKVN/128, MM/128), 256, GEMM_SMEM>>>(h, wqkv, nullptr, nullptr, qkvh, MM, QKVN, DD);
    // tensor-core flash attention (ctx bf16)
    attn_mma<<<dim3(BB*HH, SS/64), 128>>>(qkvh, ctx);
    // output projection + bias + residual x -> x1 (fp32)
    gemm_bf16<true,true,false,float><<<dim3(DD/128, MM/128), 256, GEMM_SMEM>>>(ctx, wo, bo, x, x1, MM, DD, DD);
    // LN2 (bf16 out)
    ln_kernel<<<MM, 256>>>(x1, ln2_scale, ln2_bias, h2);
    // FF1 + relu (bf16 out)
    gemm_bf16<true,false,true,__nv_bfloat16><<<dim3(FF/128, MM/128), 256, GEMM_SMEM>>>(h2, w1, b1, nullptr, ff, MM, FF, DD);
    // FF2 + bias + residual x1 -> out (fp32)
    gemm_bf16<true,true,false,float><<<dim3(DD/128, MM/128), 256, GEMM_SMEM>>>(ff, w2, b2, x1, out, MM, DD, FF);
}

// round 8
// speedup vs baseline: 5.4237x; 1.3118x over previous
#include <cuda_runtime.h>
#include <cuda_bf16.h>
#include <cstdint>
#include <math.h>

// ---------------- problem constants ----------------
#define BB 2
#define SS 2048
#define DD 1024
#define HH 16
#define HSZ 64
#define FF 4096
#define MM (BB*SS)          // 4096 rows
#define QKVN (3*DD)         // 3072

#define MNEG  (-1e30f)

typedef __nv_bfloat16 bf16;

// ---------------- scratch (static device globals; no allocation) ----------------
__device__ bf16  g_h   [MM*DD];           // LN1 output
__device__ bf16  g_wqkv[QKVN*DD];         // repacked [3072, 1024] (transposed, Wq pre-scaled)
__device__ bf16  g_qkvh[(size_t)MM*QKVN]; // QKV bf16
__device__ bf16  g_ctx [MM*DD];           // attention out
__device__ float g_x1  [MM*DD];           // post-attention residual (fp32)
__device__ bf16  g_h2  [MM*DD];           // LN2 output
__device__ bf16  g_ff  [(size_t)MM*FF];   // FF1 out
__device__ bf16  g_wo  [DD*DD];           // [1024,1024] transposed
__device__ bf16  g_w1  [FF*DD];           // [4096,1024] transposed
__device__ bf16  g_w2  [DD*FF];           // [1024,4096] transposed

// ---------------- cp.async helpers ----------------
__device__ __forceinline__ unsigned smem_u32(const void* p) {
    return (unsigned)__cvta_generic_to_shared(p);
}
__device__ __forceinline__ void cp16(void* smem, const void* gmem) {
    unsigned s = smem_u32(smem);
    asm volatile("cp.async.cg.shared.global [%0], [%1], 16;\n" :: "r"(s), "l"(gmem));
}
#define CP_COMMIT asm volatile("cp.async.commit_group;\n" ::: "memory")
#define CP_WAIT1  asm volatile("cp.async.wait_group 1;\n" ::: "memory")
#define CP_WAIT0  asm volatile("cp.async.wait_group 0;\n" ::: "memory")

// ---------------- mma / ldmatrix primitives ----------------
__device__ __forceinline__ void ldmx2(unsigned a, unsigned &r0, unsigned &r1) {
    asm volatile("ldmatrix.sync.aligned.m8n8.x2.shared.b16 {%0,%1}, [%2];"
                 : "=r"(r0), "=r"(r1) : "r"(a));
}
__device__ __forceinline__ void ldmx2t(unsigned a, unsigned &r0, unsigned &r1) {
    asm volatile("ldmatrix.sync.aligned.m8n8.x2.trans.shared.b16 {%0,%1}, [%2];"
                 : "=r"(r0), "=r"(r1) : "r"(a));
}
__device__ __forceinline__ void ldmx4(unsigned a, unsigned &r0, unsigned &r1, unsigned &r2, unsigned &r3) {
    asm volatile("ldmatrix.sync.aligned.m8n8.x4.shared.b16 {%0,%1,%2,%3}, [%4];"
                 : "=r"(r0), "=r"(r1), "=r"(r2), "=r"(r3) : "r"(a));
}
__device__ __forceinline__ void mma_bf16(float* c, const unsigned* a, unsigned b0, unsigned b1) {
    asm volatile("mma.sync.aligned.m16n8k16.row.col.f32.bf16.bf16.f32 "
                 "{%0,%1,%2,%3}, {%4,%5,%6,%7}, {%8,%9}, {%0,%1,%2,%3};"
                 : "+f"(c[0]), "+f"(c[1]), "+f"(c[2]), "+f"(c[3])
                 : "r"(a[0]), "r"(a[1]), "r"(a[2]), "r"(a[3]), "r"(b0), "r"(b1));
}
__device__ __forceinline__ unsigned pk_bf2(float x, float y) {
    __nv_bfloat162 v = __floats2bfloat162_rn(x, y);
    return *(unsigned*)&v;
}

// ---------------- LayerNorm: one block per row, 256 threads, bf16 out ----------------
__global__ __launch_bounds__(256) void ln_kernel(const float* __restrict__ in,
                                                 const float* __restrict__ sc,
                                                 const float* __restrict__ bi,
                                                 bf16* __restrict__ out)
{
    int row = blockIdx.x;
    const float* x = in + (size_t)row * DD;
    float v[4];
    float s = 0.f, sq = 0.f;
#pragma unroll
    for (int i = 0; i < 4; i++) {
        v[i] = x[threadIdx.x + i*256];
        s  += v[i];
        sq += v[i]*v[i];
    }
#pragma unroll
    for (int off = 16; off; off >>= 1) {
        s  += __shfl_xor_sync(0xFFFFFFFFu, s,  off);
        sq += __shfl_xor_sync(0xFFFFFFFFu, sq, off);
    }
    __shared__ float ws[8], wq[8];
    int w = threadIdx.x >> 5, ln = threadIdx.x & 31;
    if (ln == 0) { ws[w] = s; wq[w] = sq; }
    __syncthreads();
    s = 0.f; sq = 0.f;
#pragma unroll
    for (int i = 0; i < 8; i++) { s += ws[i]; sq += wq[i]; }
    float mu  = s * (1.f/DD);
    float var = sq * (1.f/DD) - mu*mu;
    float r   = rsqrtf(var + 1e-5f);
    bf16* o = out + (size_t)row * DD;
#pragma unroll
    for (int i = 0; i < 4; i++) {
        int c = threadIdx.x + i*256;
        o[c] = __float2bfloat16_rn((v[i] - mu) * r * sc[c] + bi[c]);
    }
}

// ---------------- QKV weight transpose-repack ----------------
// Wq/Wk/Wv [H, D, HS] fp32 -> wqkv [3072, 1024] bf16 (row n = m*1024 + h*64 + e, col d)
__global__ __launch_bounds__(256) void qkv_trans(const float* __restrict__ Wq,
                                                 const float* __restrict__ Wk,
                                                 const float* __restrict__ Wv,
                                                 bf16* __restrict__ out)
{
    __shared__ float t[32][33];
    int mh = blockIdx.z;
    int m = mh >> 4, h = mh & 15;
    const float* in = (m == 0 ? Wq : (m == 1 ? Wk : Wv)) + (size_t)h * DD * HSZ;
    float scl = (m == 0) ? 0.03125f : 1.0f;   // fold D^-0.5 into Wq
    int d0 = blockIdx.x * 32, e0 = blockIdx.y * 32;
    int tx = threadIdx.x & 31, ty = threadIdx.x >> 5;
#pragma unroll
    for (int i = 0; i < 4; i++)
        t[ty + 8*i][tx] = in[(size_t)(d0 + ty + 8*i) * HSZ + e0 + tx];
    __syncthreads();
    bf16* ob = out + ((size_t)m * DD + h * HSZ) * DD;
#pragma unroll
    for (int i = 0; i < 4; i++)
        ob[(size_t)(e0 + ty + 8*i) * DD + d0 + tx] = __float2bfloat16_rn(t[tx][ty + 8*i] * scl);
}

// ---------------- generic weight transpose: in [R,C] fp32 -> out [C,R] bf16 ----------------
__global__ __launch_bounds__(256) void wtrans(const float* __restrict__ in,
                                              bf16* __restrict__ out, int R, int C)
{
    __shared__ float t[32][33];
    int r0 = blockIdx.x * 32, c0 = blockIdx.y * 32;
    int tx = threadIdx.x & 31, ty = threadIdx.x >> 5;
#pragma unroll
    for (int i = 0; i < 4; i++)
        t[ty + 8*i][tx] = in[(size_t)(r0 + ty + 8*i) * C + c0 + tx];
    __syncthreads();
#pragma unroll
    for (int i = 0; i < 4; i++)
        out[(size_t)(c0 + ty + 8*i) * R + r0 + tx] = __float2bfloat16_rn(t[tx][ty + 8*i]);
}

// ---------------- raw-mma bf16 GEMM ----------------
// C[M,N] = A[M,K] @ Bt[N,K]^T (+bias)(+res)(relu). A,Bt bf16 K-major.
// CTA 128x128, 4 warps (2x2), warp tile 64x64, BK=32, 3-stage cp.async.
#define ALD 40                     // smem pitch in bf16 (80B): conflict-free ldmatrix
#define STAGE_E (128*ALD)          // elems per matrix stage
#define GEMM_SMEM (6*STAGE_E*2)    // 61440 bytes

__device__ __forceinline__ void store2(float* p, float v0, float v1) {
    *(float2*)p = make_float2(v0, v1);
}
__device__ __forceinline__ void store2(bf16* p, float v0, float v1) {
    *(__nv_bfloat162*)p = __floats2bfloat162_rn(v0, v1);
}

template<bool BIAS, bool RES, bool RELU, typename OutT>
__global__ __launch_bounds__(128) void gemm_mma(const bf16* __restrict__ A,
                                                const bf16* __restrict__ Bt,
                                                const float* __restrict__ bias,
                                                const float* __restrict__ res,
                                                OutT* __restrict__ C,
                                                int M, int N, int K)
{
    extern __shared__ bf16 sm[];
    bf16* As = sm;
    bf16* Bs = sm + 3*STAGE_E;

    int tid  = threadIdx.x;
    int w    = tid >> 5;
    int lane = tid & 31;
    int wm   = w & 1;           // 0..1: 64-row slice
    int wn   = w >> 1;          // 0..1: 64-col slice
    int rowBlock = blockIdx.y * 128;
    int colBlock = blockIdx.x * 128;

    const bf16* Ag = A  + (size_t)(rowBlock + tid) * K;   // one row per thread
    const bf16* Bg = Bt + (size_t)(colBlock + tid) * K;

    auto prefetch = [&](int st, int kb) {
        bf16* as = As + st*STAGE_E + tid*ALD;
        bf16* bs = Bs + st*STAGE_E + tid*ALD;
#pragma unroll
        for (int i = 0; i < 4; i++) {
            cp16(as + i*8, Ag + kb + i*8);
            cp16(bs + i*8, Bg + kb + i*8);
        }
        CP_COMMIT;
    };

    float acc[4][8][4];
#pragma unroll
    for (int mt = 0; mt < 4; mt++)
#pragma unroll
        for (int nt = 0; nt < 8; nt++)
#pragma unroll
            for (int e = 0; e < 4; e++) acc[mt][nt][e] = 0.f;

    prefetch(0, 0);
    prefetch(1, 32);

    // ldmatrix lane-address components
    int a_r8 = (lane & 7) + ((lane >> 3) & 1) * 8;   // row within 16
    int a_c8 = ((lane >> 4) & 1) * 8;                // k half
    int b_r8 = (lane & 7) + ((lane >> 4) & 1) * 8;   // n row within 16
    int b_c8 = ((lane >> 3) & 1) * 8;                // k half

    int nIter = K >> 5;
    for (int kt = 0; kt < nIter; kt++) {
        if (kt == nIter - 1) { CP_WAIT0; } else { CP_WAIT1; }
        __syncthreads();
        if (kt + 2 < nIter) prefetch((kt + 2) % 3, (kt + 2) * 32);

        const bf16* as = As + (kt % 3) * STAGE_E;
        const bf16* bs = Bs + (kt % 3) * STAGE_E;
#pragma unroll
        for (int ks = 0; ks < 2; ks++) {
            unsigned af[4][4];
#pragma unroll
            for (int mt = 0; mt < 4; mt++) {
                int row = wm*64 + mt*16 + a_r8;
                ldmx4(smem_u32(as + row*ALD + ks*16 + a_c8),
                      af[mt][0], af[mt][1], af[mt][2], af[mt][3]);
            }
            unsigned bfr[8][2];
#pragma unroll
            for (int np = 0; np < 4; np++) {
                int row = wn*64 + np*16 + b_r8;
                unsigned r0, r1, r2, r3;
                ldmx4(smem_u32(bs + row*ALD + ks*16 + b_c8), r0, r1, r2, r3);
                bfr[2*np][0] = r0;  bfr[2*np][1] = r1;
                bfr[2*np+1][0] = r2; bfr[2*np+1][1] = r3;
            }
#pragma unroll
            for (int mt = 0; mt < 4; mt++)
#pragma unroll
                for (int nt = 0; nt < 8; nt++)
                    mma_bf16(acc[mt][nt], af[mt], bfr[nt][0], bfr[nt][1]);
        }
        __syncthreads();
    }

    // epilogue: direct stores, postops fused
#pragma unroll
    for (int mt = 0; mt < 4; mt++) {
        int r0 = rowBlock + wm*64 + mt*16 + (lane >> 2);
#pragma unroll
        for (int nt = 0; nt < 8; nt++) {
            int col = colBlock + wn*64 + nt*8 + (lane & 3)*2;
            float v0 = acc[mt][nt][0], v1 = acc[mt][nt][1];
            float v2 = acc[mt][nt][2], v3 = acc[mt][nt][3];
            if (BIAS) {
                float b0 = bias[col], b1 = bias[col + 1];
                v0 += b0; v1 += b1; v2 += b0; v3 += b1;
            }
            size_t o0 = (size_t)r0 * N + col;
            size_t o1 = (size_t)(r0 + 8) * N + col;
            if (RES) {
                v0 += res[o0]; v1 += res[o0 + 1];
                v2 += res[o1]; v3 += res[o1 + 1];
            }
            if (RELU) {
                v0 = fmaxf(v0, 0.f); v1 = fmaxf(v1, 0.f);
                v2 = fmaxf(v2, 0.f); v3 = fmaxf(v3, 0.f);
            }
            store2(&C[o0], v0, v1);
            store2(&C[o1], v2, v3);
        }
    }
}

// ---------------- Tensor-core flash attention (causal) ----------------
// Br=64 rows/block (4 warps x 16 rows), Bc=64 keys/tile. qkv bf16, Q pre-scaled.
#define AP 72   // smem pitch (bf16 elems) = 144B -> conflict-free ldmatrix

__global__ __launch_bounds__(128) void attn_mma(const bf16* __restrict__ qkv,
                                                bf16* __restrict__ ctx)
{
    __shared__ bf16 Qs[64][AP];
    __shared__ bf16 Ks[2][64][AP];
    __shared__ bf16 Vs[2][64][AP];

    int bh = blockIdx.x;
    int b = bh >> 4, h = bh & 15;
    int qt = (int)gridDim.y - 1 - (int)blockIdx.y;   // heavy tiles first
    int tid = threadIdx.x;
    int w = tid >> 5, lane = tid & 31;
    int g = lane >> 2, t = lane & 3;

    const bf16* base = qkv + (size_t)(b*SS) * QKVN + h*HSZ;
    int ntiles = qt + 1;

    int lr = tid >> 3, lc = (tid & 7) * 8;

#pragma unroll
    for (int i = 0; i < 4; i++) {
        int rr = lr + i*16;
        cp16(&Qs[rr][lc], base + (size_t)(64*qt + rr) * QKVN + lc);
    }
    CP_COMMIT;

    auto loadKV = [&](int st, int kt) {
        const bf16* kb = base + DD     + (size_t)(64*kt) * QKVN;
        const bf16* vb = base + 2*DD   + (size_t)(64*kt) * QKVN;
#pragma unroll
        for (int i = 0; i < 4; i++) {
            int rr = lr + i*16;
            cp16(&Ks[st][rr][lc], kb + (size_t)rr * QKVN + lc);
            cp16(&Vs[st][rr][lc], vb + (size_t)rr * QKVN + lc);
        }
        CP_COMMIT;
    };

    loadKV(0, 0);
    if (ntiles > 1) loadKV(1, 1);
    if (ntiles > 1) { CP_WAIT1; } else { CP_WAIT0; }
    __syncthreads();

    unsigned qf[4][4];
    {
        int qrow = w*16 + (lane & 7) + ((lane >> 3) & 1) * 8;
        int qcol = (lane >> 4) * 8;
#pragma unroll
        for (int kc = 0; kc < 4; kc++)
            ldmx4(smem_u32(&Qs[qrow][kc*16 + qcol]), qf[kc][0], qf[kc][1], qf[kc][2], qf[kc][3]);
    }

    float O[8][4];
#pragma unroll
    for (int j = 0; j < 8; j++)
#pragma unroll
        for (int e = 0; e < 4; e++) O[j][e] = 0.f;
    float m_lo = MNEG, m_hi = MNEG, l_lo = 0.f, l_hi = 0.f;

    for (int kt = 0; kt < ntiles; kt++) {
        int st = kt & 1;

        float S[8][4];
#pragma unroll
        for (int j = 0; j < 8; j++)
#pragma unroll
            for (int e = 0; e < 4; e++) S[j][e] = 0.f;

        int l15 = lane & 15;
#pragma unroll
        for (int j = 0; j < 8; j++) {
#pragma unroll
            for (int kc = 0; kc < 4; kc++) {
                unsigned b0, b1;
                int krow = 8*j + (l15 & 7);
                int kcol = kc*16 + ((l15 >> 3) & 1) * 8;
                ldmx2(smem_u32(&Ks[st][krow][kcol]), b0, b1);
                mma_bf16(S[j], qf[kc], b0, b1);
            }
        }

        if (kt == qt) {
            int lim_lo = w*16 + g;
            int lim_hi = lim_lo + 8;
#pragma unroll
            for (int j = 0; j < 8; j++) {
                int c0 = 8*j + 2*t;
                if (c0     > lim_lo) S[j][0] = MNEG;
                if (c0 + 1 > lim_lo) S[j][1] = MNEG;
                if (c0     > lim_hi) S[j][2] = MNEG;
                if (c0 + 1 > lim_hi) S[j][3] = MNEG;
            }
        }

        float mx_lo = MNEG, mx_hi = MNEG;
#pragma unroll
        for (int j = 0; j < 8; j++) {
            mx_lo = fmaxf(mx_lo, fmaxf(S[j][0], S[j][1]));
            mx_hi = fmaxf(mx_hi, fmaxf(S[j][2], S[j][3]));
        }
        mx_lo = fmaxf(mx_lo, __shfl_xor_sync(0xFFFFFFFFu, mx_lo, 1));
        mx_lo = fmaxf(mx_lo, __shfl_xor_sync(0xFFFFFFFFu, mx_lo, 2));
        mx_hi = fmaxf(mx_hi, __shfl_xor_sync(0xFFFFFFFFu, mx_hi, 1));
        mx_hi = fmaxf(mx_hi, __shfl_xor_sync(0xFFFFFFFFu, mx_hi, 2));

        float nm_lo = fmaxf(m_lo, mx_lo);
        float nm_hi = fmaxf(m_hi, mx_hi);
        float corr_lo = __expf(m_lo - nm_lo);
        float corr_hi = __expf(m_hi - nm_hi);
        m_lo = nm_lo; m_hi = nm_hi;

        float sum_lo = 0.f, sum_hi = 0.f;
        unsigned pf[4][4];
#pragma unroll
        for (int kc = 0; kc < 4; kc++) {
            int j0 = 2*kc, j1 = 2*kc + 1;
            float p00 = __expf(S[j0][0] - m_lo), p01 = __expf(S[j0][1] - m_lo);
            float p02 = __expf(S[j0][2] - m_hi), p03 = __expf(S[j0][3] - m_hi);
            float p10 = __expf(S[j1][0] - m_lo), p11 = __expf(S[j1][1] - m_lo);
            float p12 = __expf(S[j1][2] - m_hi), p13 = __expf(S[j1][3] - m_hi);
            sum_lo += (p00 + p01) + (p10 + p11);
            sum_hi += (p02 + p03) + (p12 + p13);
            pf[kc][0] = pk_bf2(p00, p01);
            pf[kc][1] = pk_bf2(p02, p03);
            pf[kc][2] = pk_bf2(p10, p11);
            pf[kc][3] = pk_bf2(p12, p13);
        }
        sum_lo += __shfl_xor_sync(0xFFFFFFFFu, sum_lo, 1);
        sum_lo += __shfl_xor_sync(0xFFFFFFFFu, sum_lo, 2);
        sum_hi += __shfl_xor_sync(0xFFFFFFFFu, sum_hi, 1);
        sum_hi += __shfl_xor_sync(0xFFFFFFFFu, sum_hi, 2);
        l_lo = l_lo * corr_lo + sum_lo;
        l_hi = l_hi * corr_hi + sum_hi;

#pragma unroll
        for (int j = 0; j < 8; j++) {
            O[j][0] *= corr_lo; O[j][1] *= corr_lo;
            O[j][2] *= corr_hi; O[j][3] *= corr_hi;
        }

#pragma unroll
        for (int j = 0; j < 8; j++) {
#pragma unroll
            for (int kc = 0; kc < 4; kc++) {
                unsigned b0, b1;
                int vrow = 16*kc + ((l15 >> 3) & 1) * 8 + (l15 & 7);
                ldmx2t(smem_u32(&Vs[st][vrow][8*j]), b0, b1);
                mma_bf16(O[j], pf[kc], b0, b1);
            }
        }

        __syncthreads();
        if (kt + 2 < ntiles) loadKV(st, kt + 2);
        if (kt + 1 < ntiles) {
            if (kt + 2 < ntiles) { CP_WAIT1; } else { CP_WAIT0; }
            __syncthreads();
        }
    }

    float il_lo = 1.f / l_lo, il_hi = 1.f / l_hi;
    bf16* obase = ctx + (size_t)(b*SS + 64*qt + w*16) * DD + h*HSZ;
#pragma unroll
    for (int j = 0; j < 8; j++) {
        int col = 8*j + 2*t;
        *(__nv_bfloat162*)(obase + (size_t)g       * DD + col) = __floats2bfloat162_rn(O[j][0]*il_lo, O[j][1]*il_lo);
        *(__nv_bfloat162*)(obase + (size_t)(g + 8) * DD + col) = __floats2bfloat162_rn(O[j][2]*il_hi, O[j][3]*il_hi);
    }
}

// ---------------- host launcher ----------------
extern "C" void kernel_launch(void* const* d_in, const int* in_sizes, int n_in,
                              void* d_out, int out_size)
{
    const float* x         = (const float*)d_in[0];
    const float* ln1_scale = (const float*)d_in[1];
    const float* ln1_bias  = (const float*)d_in[2];
    const float* Wq        = (const float*)d_in[3];
    const float* Wk        = (const float*)d_in[4];
    const float* Wv        = (const float*)d_in[5];
    const float* Wo        = (const float*)d_in[6];
    const float* bo        = (const float*)d_in[7];
    const float* ln2_scale = (const float*)d_in[8];
    const float* ln2_bias  = (const float*)d_in[9];
    const float* W1        = (const float*)d_in[10];
    const float* b1        = (const float*)d_in[11];
    const float* W2        = (const float*)d_in[12];
    const float* b2        = (const float*)d_in[13];
    float* out = (float*)d_out;

    bf16 *h, *wqkv, *qkvh, *ctx, *h2, *ff, *wo, *w1, *w2;
    float *x1;
    cudaGetSymbolAddress((void**)&h,    g_h);
    cudaGetSymbolAddress((void**)&wqkv, g_wqkv);
    cudaGetSymbolAddress((void**)&qkvh, g_qkvh);
    cudaGetSymbolAddress((void**)&ctx,  g_ctx);
    cudaGetSymbolAddress((void**)&x1,   g_x1);
    cudaGetSymbolAddress((void**)&h2,   g_h2);
    cudaGetSymbolAddress((void**)&ff,   g_ff);
    cudaGetSymbolAddress((void**)&wo,   g_wo);
    cudaGetSymbolAddress((void**)&w1,   g_w1);
    cudaGetSymbolAddress((void**)&w2,   g_w2);

    cudaFuncSetAttribute(gemm_mma<false,false,false,bf16>,
                         cudaFuncAttributeMaxDynamicSharedMemorySize, GEMM_SMEM);
    cudaFuncSetAttribute(gemm_mma<true,true,false,float>,
                         cudaFuncAttributeMaxDynamicSharedMemorySize, GEMM_SMEM);
    cudaFuncSetAttribute(gemm_mma<true,false,true,bf16>,
                         cudaFuncAttributeMaxDynamicSharedMemorySize, GEMM_SMEM);

    // weight prep: transpose to [N, K] bf16
    qkv_trans<<<dim3(32, 2, 48), 256>>>(Wq, Wk, Wv, wqkv);
    wtrans<<<dim3(32, 32), 256>>>(Wo, wo, DD, DD);
    wtrans<<<dim3(32, 128), 256>>>(W1, w1, DD, FF);
    wtrans<<<dim3(128, 32), 256>>>(W2, w2, FF, DD);

    // LN1 (bf16 out)
    ln_kernel<<<MM, 256>>>(x, ln1_scale, ln1_bias, h);
    // QKV projection -> bf16 (Q pre-scaled via Wq)
    gemm_mma<false,false,false,bf16><<<dim3(QKVN/128, MM/128), 128, GEMM_SMEM>>>(h, wqkv, nullptr, nullptr, qkvh, MM, QKVN, DD);
    // tensor-core flash attention (ctx bf16)
    attn_mma<<<dim3(BB*HH, SS/64), 128>>>(qkvh, ctx);
    // output projection + bias + residual x -> x1 (fp32)
    gemm_mma<true,true,false,float><<<dim3(DD/128, MM/128), 128, GEMM_SMEM>>>(ctx, wo, bo, x, x1, MM, DD, DD);
    // LN2 (bf16 out)
    ln_kernel<<<MM, 256>>>(x1, ln2_scale, ln2_bias, h2);
    // FF1 + relu (bf16 out)
    gemm_mma<true,false,true,bf16><<<dim3(FF/128, MM/128), 128, GEMM_SMEM>>>(h2, w1, b1, nullptr, ff, MM, FF, DD);
    // FF2 + bias + residual x1 -> out (fp32)
    gemm_mma<true,true,false,float><<<dim3(DD/128, MM/128), 128, GEMM_SMEM>>>(ff, w2, b2, x1, out, MM, DD, FF);
}

// round 9
// speedup vs baseline: 5.6093x; 1.0342x over previous
#include <cuda_runtime.h>
#include <cuda_bf16.h>
#include <cstdint>
#include <math.h>

// ---------------- problem constants ----------------
#define BB 2
#define SS 2048
#define DD 1024
#define HH 16
#define HSZ 64
#define FF 4096
#define MM (BB*SS)          // 4096 rows
#define QKVN (3*DD)         // 3072

#define MNEG  (-1e30f)

typedef __nv_bfloat16 bf16;

// ---------------- scratch (static device globals; no allocation) ----------------
__device__ bf16  g_h   [MM*DD];           // LN1 output
__device__ bf16  g_wqkv[QKVN*DD];         // repacked [3072, 1024] (transposed, Wq pre-scaled)
__device__ bf16  g_qkvh[(size_t)MM*QKVN]; // QKV bf16
__device__ bf16  g_ctx [MM*DD];           // attention out
__device__ float g_x1  [MM*DD];           // post-attention residual (fp32)
__device__ bf16  g_h2  [MM*DD];           // LN2 output
__device__ bf16  g_ff  [(size_t)MM*FF];   // FF1 out
__device__ bf16  g_wo  [DD*DD];           // [1024,1024] transposed
__device__ bf16  g_w1  [FF*DD];           // [4096,1024] transposed
__device__ bf16  g_w2  [DD*FF];           // [1024,4096] transposed

// ---------------- cp.async helpers ----------------
__device__ __forceinline__ unsigned smem_u32(const void* p) {
    return (unsigned)__cvta_generic_to_shared(p);
}
__device__ __forceinline__ void cp16(void* smem, const void* gmem) {
    unsigned s = smem_u32(smem);
    asm volatile("cp.async.cg.shared.global [%0], [%1], 16;\n" :: "r"(s), "l"(gmem));
}
#define CP_COMMIT asm volatile("cp.async.commit_group;\n" ::: "memory")
#define CP_WAIT1  asm volatile("cp.async.wait_group 1;\n" ::: "memory")
#define CP_WAIT0  asm volatile("cp.async.wait_group 0;\n" ::: "memory")

// ---------------- mma / ldmatrix primitives ----------------
__device__ __forceinline__ void ldmx2(unsigned a, unsigned &r0, unsigned &r1) {
    asm volatile("ldmatrix.sync.aligned.m8n8.x2.shared.b16 {%0,%1}, [%2];"
                 : "=r"(r0), "=r"(r1) : "r"(a));
}
__device__ __forceinline__ void ldmx2t(unsigned a, unsigned &r0, unsigned &r1) {
    asm volatile("ldmatrix.sync.aligned.m8n8.x2.trans.shared.b16 {%0,%1}, [%2];"
                 : "=r"(r0), "=r"(r1) : "r"(a));
}
__device__ __forceinline__ void ldmx4(unsigned a, unsigned &r0, unsigned &r1, unsigned &r2, unsigned &r3) {
    asm volatile("ldmatrix.sync.aligned.m8n8.x4.shared.b16 {%0,%1,%2,%3}, [%4];"
                 : "=r"(r0), "=r"(r1), "=r"(r2), "=r"(r3) : "r"(a));
}
__device__ __forceinline__ void mma_bf16(float* c, const unsigned* a, unsigned b0, unsigned b1) {
    asm volatile("mma.sync.aligned.m16n8k16.row.col.f32.bf16.bf16.f32 "
                 "{%0,%1,%2,%3}, {%4,%5,%6,%7}, {%8,%9}, {%0,%1,%2,%3};"
                 : "+f"(c[0]), "+f"(c[1]), "+f"(c[2]), "+f"(c[3])
                 : "r"(a[0]), "r"(a[1]), "r"(a[2]), "r"(a[3]), "r"(b0), "r"(b1));
}
__device__ __forceinline__ unsigned pk_bf2(float x, float y) {
    __nv_bfloat162 v = __floats2bfloat162_rn(x, y);
    return *(unsigned*)&v;
}

// ---------------- LayerNorm: one block per row, 256 threads, bf16 out ----------------
__global__ __launch_bounds__(256) void ln_kernel(const float* __restrict__ in,
                                                 const float* __restrict__ sc,
                                                 const float* __restrict__ bi,
                                                 bf16* __restrict__ out)
{
    int row = blockIdx.x;
    const float* x = in + (size_t)row * DD;
    float v[4];
    float s = 0.f, sq = 0.f;
#pragma unroll
    for (int i = 0; i < 4; i++) {
        v[i] = x[threadIdx.x + i*256];
        s  += v[i];
        sq += v[i]*v[i];
    }
#pragma unroll
    for (int off = 16; off; off >>= 1) {
        s  += __shfl_xor_sync(0xFFFFFFFFu, s,  off);
        sq += __shfl_xor_sync(0xFFFFFFFFu, sq, off);
    }
    __shared__ float ws[8], wq[8];
    int w = threadIdx.x >> 5, ln = threadIdx.x & 31;
    if (ln == 0) { ws[w] = s; wq[w] = sq; }
    __syncthreads();
    s = 0.f; sq = 0.f;
#pragma unroll
    for (int i = 0; i < 8; i++) { s += ws[i]; sq += wq[i]; }
    float mu  = s * (1.f/DD);
    float var = sq * (1.f/DD) - mu*mu;
    float r   = rsqrtf(var + 1e-5f);
    bf16* o = out + (size_t)row * DD;
#pragma unroll
    for (int i = 0; i < 4; i++) {
        int c = threadIdx.x + i*256;
        o[c] = __float2bfloat16_rn((v[i] - mu) * r * sc[c] + bi[c]);
    }
}

// ---------------- QKV weight transpose-repack ----------------
// Wq/Wk/Wv [H, D, HS] fp32 -> wqkv [3072, 1024] bf16 (row n = m*1024 + h*64 + e, col d)
__global__ __launch_bounds__(256) void qkv_trans(const float* __restrict__ Wq,
                                                 const float* __restrict__ Wk,
                                                 const float* __restrict__ Wv,
                                                 bf16* __restrict__ out)
{
    __shared__ float t[32][33];
    int mh = blockIdx.z;
    int m = mh >> 4, h = mh & 15;
    const float* in = (m == 0 ? Wq : (m == 1 ? Wk : Wv)) + (size_t)h * DD * HSZ;
    float scl = (m == 0) ? 0.03125f : 1.0f;   // fold D^-0.5 into Wq
    int d0 = blockIdx.x * 32, e0 = blockIdx.y * 32;
    int tx = threadIdx.x & 31, ty = threadIdx.x >> 5;
#pragma unroll
    for (int i = 0; i < 4; i++)
        t[ty + 8*i][tx] = in[(size_t)(d0 + ty + 8*i) * HSZ + e0 + tx];
    __syncthreads();
    bf16* ob = out + ((size_t)m * DD + h * HSZ) * DD;
#pragma unroll
    for (int i = 0; i < 4; i++)
        ob[(size_t)(e0 + ty + 8*i) * DD + d0 + tx] = __float2bfloat16_rn(t[tx][ty + 8*i] * scl);
}

// ---------------- generic weight transpose: in [R,C] fp32 -> out [C,R] bf16 ----------------
__global__ __launch_bounds__(256) void wtrans(const float* __restrict__ in,
                                              bf16* __restrict__ out, int R, int C)
{
    __shared__ float t[32][33];
    int r0 = blockIdx.x * 32, c0 = blockIdx.y * 32;
    int tx = threadIdx.x & 31, ty = threadIdx.x >> 5;
#pragma unroll
    for (int i = 0; i < 4; i++)
        t[ty + 8*i][tx] = in[(size_t)(r0 + ty + 8*i) * C + c0 + tx];
    __syncthreads();
#pragma unroll
    for (int i = 0; i < 4; i++)
        out[(size_t)(c0 + ty + 8*i) * R + r0 + tx] = __float2bfloat16_rn(t[tx][ty + 8*i]);
}

// ---------------- raw-mma bf16 GEMM ----------------
// C[M,N] = A[M,K] @ Bt[N,K]^T (+bias)(+res)(relu). A,Bt bf16 K-major.
// CTA 128x256, 8 warps (2x4), warp tile 64x64, BK=32, 3-stage cp.async, 1 sync/iter.
#define ALD 40                      // smem pitch in bf16 (80B): conflict-free ldmatrix
#define STAGE_A (128*ALD)
#define STAGE_B (256*ALD)
#define STAGE_E (STAGE_A + STAGE_B)
#define GEMM_SMEM (3*STAGE_E*2)     // 92160 bytes

__device__ __forceinline__ void store2(float* p, float v0, float v1) {
    *(float2*)p = make_float2(v0, v1);
}
__device__ __forceinline__ void store2(bf16* p, float v0, float v1) {
    *(__nv_bfloat162*)p = __floats2bfloat162_rn(v0, v1);
}

template<bool BIAS, bool RES, bool RELU, typename OutT>
__global__ __launch_bounds__(256) void gemm_mma(const bf16* __restrict__ A,
                                                const bf16* __restrict__ Bt,
                                                const float* __restrict__ bias,
                                                const float* __restrict__ res,
                                                OutT* __restrict__ C,
                                                int M, int N, int K)
{
    extern __shared__ bf16 sm[];

    int tid  = threadIdx.x;
    int w    = tid >> 5;
    int lane = tid & 31;
    int wm   = w & 1;           // 0..1: 64-row slice
    int wn   = w >> 1;          // 0..3: 64-col slice
    int rowBlock = blockIdx.y * 128;
    int colBlock = blockIdx.x * 256;

    // loaders: A row tid>>1 (half row each), B row tid (full row)
    int a_r = tid >> 1, a_c = (tid & 1) * 16;
    const bf16* Ag = A  + (size_t)(rowBlock + a_r) * K + a_c;
    const bf16* Bg = Bt + (size_t)(colBlock + tid) * K;

    auto prefetch = [&](int st, int kb) {
        bf16* as = sm + st*STAGE_E + a_r*ALD + a_c;
        bf16* bs = sm + st*STAGE_E + STAGE_A + tid*ALD;
        cp16(as,     Ag + kb);
        cp16(as + 8, Ag + kb + 8);
#pragma unroll
        for (int i = 0; i < 4; i++)
            cp16(bs + i*8, Bg + kb + i*8);
        CP_COMMIT;
    };

    float acc[4][8][4];
#pragma unroll
    for (int mt = 0; mt < 4; mt++)
#pragma unroll
        for (int nt = 0; nt < 8; nt++)
#pragma unroll
            for (int e = 0; e < 4; e++) acc[mt][nt][e] = 0.f;

    prefetch(0, 0);
    prefetch(1, 32);

    // ldmatrix lane-address components
    int a_r8 = (lane & 7) + ((lane >> 3) & 1) * 8;   // row within 16
    int a_c8 = ((lane >> 4) & 1) * 8;                // k half
    int b_r8 = (lane & 7) + ((lane >> 4) & 1) * 8;   // n row within 16
    int b_c8 = ((lane >> 3) & 1) * 8;                // k half

    int nIter = K >> 5;
    for (int kt = 0; kt < nIter; kt++) {
        if (kt == nIter - 1) { CP_WAIT0; } else { CP_WAIT1; }
        __syncthreads();
        if (kt + 2 < nIter) prefetch((kt + 2) % 3, (kt + 2) * 32);

        const bf16* as = sm + (kt % 3) * STAGE_E;
        const bf16* bs = as + STAGE_A;

        unsigned af[2][4][4];
        unsigned bfr[2][8][2];
        // load fragments for ks=0
#pragma unroll
        for (int mt = 0; mt < 4; mt++) {
            int row = wm*64 + mt*16 + a_r8;
            ldmx4(smem_u32(as + row*ALD + a_c8),
                  af[0][mt][0], af[0][mt][1], af[0][mt][2], af[0][mt][3]);
        }
#pragma unroll
        for (int np = 0; np < 4; np++) {
            int row = wn*64 + np*16 + b_r8;
            unsigned r0, r1, r2, r3;
            ldmx4(smem_u32(bs + row*ALD + b_c8), r0, r1, r2, r3);
            bfr[0][2*np][0] = r0;   bfr[0][2*np][1] = r1;
            bfr[0][2*np+1][0] = r2; bfr[0][2*np+1][1] = r3;
        }
        // load fragments for ks=1 (overlaps with ks=0 mma below via scheduler)
#pragma unroll
        for (int mt = 0; mt < 4; mt++) {
            int row = wm*64 + mt*16 + a_r8;
            ldmx4(smem_u32(as + row*ALD + 16 + a_c8),
                  af[1][mt][0], af[1][mt][1], af[1][mt][2], af[1][mt][3]);
        }
#pragma unroll
        for (int np = 0; np < 4; np++) {
            int row = wn*64 + np*16 + b_r8;
            unsigned r0, r1, r2, r3;
            ldmx4(smem_u32(bs + row*ALD + 16 + b_c8), r0, r1, r2, r3);
            bfr[1][2*np][0] = r0;   bfr[1][2*np][1] = r1;
            bfr[1][2*np+1][0] = r2; bfr[1][2*np+1][1] = r3;
        }
#pragma unroll
        for (int ks = 0; ks < 2; ks++)
#pragma unroll
            for (int mt = 0; mt < 4; mt++)
#pragma unroll
                for (int nt = 0; nt < 8; nt++)
                    mma_bf16(acc[mt][nt], af[ks][mt], bfr[ks][nt][0], bfr[ks][nt][1]);
    }

    // epilogue: direct stores, postops fused
#pragma unroll
    for (int mt = 0; mt < 4; mt++) {
        int r0 = rowBlock + wm*64 + mt*16 + (lane >> 2);
#pragma unroll
        for (int nt = 0; nt < 8; nt++) {
            int col = colBlock + wn*64 + nt*8 + (lane & 3)*2;
            float v0 = acc[mt][nt][0], v1 = acc[mt][nt][1];
            float v2 = acc[mt][nt][2], v3 = acc[mt][nt][3];
            if (BIAS) {
                float b0 = bias[col], b1 = bias[col + 1];
                v0 += b0; v1 += b1; v2 += b0; v3 += b1;
            }
            size_t o0 = (size_t)r0 * N + col;
            size_t o1 = (size_t)(r0 + 8) * N + col;
            if (RES) {
                v0 += res[o0]; v1 += res[o0 + 1];
                v2 += res[o1]; v3 += res[o1 + 1];
            }
            if (RELU) {
                v0 = fmaxf(v0, 0.f); v1 = fmaxf(v1, 0.f);
                v2 = fmaxf(v2, 0.f); v3 = fmaxf(v3, 0.f);
            }
            store2(&C[o0], v0, v1);
            store2(&C[o1], v2, v3);
        }
    }
}

// ---------------- Tensor-core flash attention (causal) ----------------
// Br=64 rows/block (4 warps x 16 rows), Bc=64 keys/tile. qkv bf16, Q pre-scaled.
#define AP 72   // smem pitch (bf16 elems) = 144B -> conflict-free ldmatrix

__global__ __launch_bounds__(128) void attn_mma(const bf16* __restrict__ qkv,
                                                bf16* __restrict__ ctx)
{
    __shared__ bf16 Qs[64][AP];
    __shared__ bf16 Ks[2][64][AP];
    __shared__ bf16 Vs[2][64][AP];

    int bh = blockIdx.x;
    int b = bh >> 4, h = bh & 15;
    int qt = (int)gridDim.y - 1 - (int)blockIdx.y;   // heavy tiles first
    int tid = threadIdx.x;
    int w = tid >> 5, lane = tid & 31;
    int g = lane >> 2, t = lane & 3;

    const bf16* base = qkv + (size_t)(b*SS) * QKVN + h*HSZ;
    int ntiles = qt + 1;

    int lr = tid >> 3, lc = (tid & 7) * 8;

#pragma unroll
    for (int i = 0; i < 4; i++) {
        int rr = lr + i*16;
        cp16(&Qs[rr][lc], base + (size_t)(64*qt + rr) * QKVN + lc);
    }
    CP_COMMIT;

    auto loadKV = [&](int st, int kt) {
        const bf16* kb = base + DD     + (size_t)(64*kt) * QKVN;
        const bf16* vb = base + 2*DD   + (size_t)(64*kt) * QKVN;
#pragma unroll
        for (int i = 0; i < 4; i++) {
            int rr = lr + i*16;
            cp16(&Ks[st][rr][lc], kb + (size_t)rr * QKVN + lc);
            cp16(&Vs[st][rr][lc], vb + (size_t)rr * QKVN + lc);
        }
        CP_COMMIT;
    };

    loadKV(0, 0);
    if (ntiles > 1) loadKV(1, 1);
    if (ntiles > 1) { CP_WAIT1; } else { CP_WAIT0; }
    __syncthreads();

    unsigned qf[4][4];
    {
        int qrow = w*16 + (lane & 7) + ((lane >> 3) & 1) * 8;
        int qcol = (lane >> 4) * 8;
#pragma unroll
        for (int kc = 0; kc < 4; kc++)
            ldmx4(smem_u32(&Qs[qrow][kc*16 + qcol]), qf[kc][0], qf[kc][1], qf[kc][2], qf[kc][3]);
    }

    float O[8][4];
#pragma unroll
    for (int j = 0; j < 8; j++)
#pragma unroll
        for (int e = 0; e < 4; e++) O[j][e] = 0.f;
    float m_lo = MNEG, m_hi = MNEG, l_lo = 0.f, l_hi = 0.f;

    for (int kt = 0; kt < ntiles; kt++) {
        int st = kt & 1;

        float S[8][4];
#pragma unroll
        for (int j = 0; j < 8; j++)
#pragma unroll
            for (int e = 0; e < 4; e++) S[j][e] = 0.f;

        int l15 = lane & 15;
#pragma unroll
        for (int j = 0; j < 8; j++) {
#pragma unroll
            for (int kc = 0; kc < 4; kc++) {
                unsigned b0, b1;
                int krow = 8*j + (l15 & 7);
                int kcol = kc*16 + ((l15 >> 3) & 1) * 8;
                ldmx2(smem_u32(&Ks[st][krow][kcol]), b0, b1);
                mma_bf16(S[j], qf[kc], b0, b1);
            }
        }

        if (kt == qt) {
            int lim_lo = w*16 + g;
            int lim_hi = lim_lo + 8;
#pragma unroll
            for (int j = 0; j < 8; j++) {
                int c0 = 8*j + 2*t;
                if (c0     > lim_lo) S[j][0] = MNEG;
                if (c0 + 1 > lim_lo) S[j][1] = MNEG;
                if (c0     > lim_hi) S[j][2] = MNEG;
                if (c0 + 1 > lim_hi) S[j][3] = MNEG;
            }
        }

        float mx_lo = MNEG, mx_hi = MNEG;
#pragma unroll
        for (int j = 0; j < 8; j++) {
            mx_lo = fmaxf(mx_lo, fmaxf(S[j][0], S[j][1]));
            mx_hi = fmaxf(mx_hi, fmaxf(S[j][2], S[j][3]));
        }
        mx_lo = fmaxf(mx_lo, __shfl_xor_sync(0xFFFFFFFFu, mx_lo, 1));
        mx_lo = fmaxf(mx_lo, __shfl_xor_sync(0xFFFFFFFFu, mx_lo, 2));
        mx_hi = fmaxf(mx_hi, __shfl_xor_sync(0xFFFFFFFFu, mx_hi, 1));
        mx_hi = fmaxf(mx_hi, __shfl_xor_sync(0xFFFFFFFFu, mx_hi, 2));

        float nm_lo = fmaxf(m_lo, mx_lo);
        float nm_hi = fmaxf(m_hi, mx_hi);
        float corr_lo = __expf(m_lo - nm_lo);
        float corr_hi = __expf(m_hi - nm_hi);
        m_lo = nm_lo; m_hi = nm_hi;

        float sum_lo = 0.f, sum_hi = 0.f;
        unsigned pf[4][4];
#pragma unroll
        for (int kc = 0; kc < 4; kc++) {
            int j0 = 2*kc, j1 = 2*kc + 1;
            float p00 = __expf(S[j0][0] - m_lo), p01 = __expf(S[j0][1] - m_lo);
            float p02 = __expf(S[j0][2] - m_hi), p03 = __expf(S[j0][3] - m_hi);
            float p10 = __expf(S[j1][0] - m_lo), p11 = __expf(S[j1][1] - m_lo);
            float p12 = __expf(S[j1][2] - m_hi), p13 = __expf(S[j1][3] - m_hi);
            sum_lo += (p00 + p01) + (p10 + p11);
            sum_hi += (p02 + p03) + (p12 + p13);
            pf[kc][0] = pk_bf2(p00, p01);
            pf[kc][1] = pk_bf2(p02, p03);
            pf[kc][2] = pk_bf2(p10, p11);
            pf[kc][3] = pk_bf2(p12, p13);
        }
        sum_lo += __shfl_xor_sync(0xFFFFFFFFu, sum_lo, 1);
        sum_lo += __shfl_xor_sync(0xFFFFFFFFu, sum_lo, 2);
        sum_hi += __shfl_xor_sync(0xFFFFFFFFu, sum_hi, 1);
        sum_hi += __shfl_xor_sync(0xFFFFFFFFu, sum_hi, 2);
        l_lo = l_lo * corr_lo + sum_lo;
        l_hi = l_hi * corr_hi + sum_hi;

#pragma unroll
        for (int j = 0; j < 8; j++) {
            O[j][0] *= corr_lo; O[j][1] *= corr_lo;
            O[j][2] *= corr_hi; O[j][3] *= corr_hi;
        }

#pragma unroll
        for (int j = 0; j < 8; j++) {
#pragma unroll
            for (int kc = 0; kc < 4; kc++) {
                unsigned b0, b1;
                int vrow = 16*kc + ((l15 >> 3) & 1) * 8 + (l15 & 7);
                ldmx2t(smem_u32(&Vs[st][vrow][8*j]), b0, b1);
                mma_bf16(O[j], pf[kc], b0, b1);
            }
        }

        __syncthreads();
        if (kt + 2 < ntiles) loadKV(st, kt + 2);
        if (kt + 1 < ntiles) {
            if (kt + 2 < ntiles) { CP_WAIT1; } else { CP_WAIT0; }
            __syncthreads();
        }
    }

    float il_lo = 1.f / l_lo, il_hi = 1.f / l_hi;
    bf16* obase = ctx + (size_t)(b*SS + 64*qt + w*16) * DD + h*HSZ;
#pragma unroll
    for (int j = 0; j < 8; j++) {
        int col = 8*j + 2*t;
        *(__nv_bfloat162*)(obase + (size_t)g       * DD + col) = __floats2bfloat162_rn(O[j][0]*il_lo, O[j][1]*il_lo);
        *(__nv_bfloat162*)(obase + (size_t)(g + 8) * DD + col) = __floats2bfloat162_rn(O[j][2]*il_hi, O[j][3]*il_hi);
    }
}

// ---------------- host launcher ----------------
extern "C" void kernel_launch(void* const* d_in, const int* in_sizes, int n_in,
                              void* d_out, int out_size)
{
    const float* x         = (const float*)d_in[0];
    const float* ln1_scale = (const float*)d_in[1];
    const float* ln1_bias  = (const float*)d_in[2];
    const float* Wq        = (const float*)d_in[3];
    const float* Wk        = (const float*)d_in[4];
    const float* Wv        = (const float*)d_in[5];
    const float* Wo        = (const float*)d_in[6];
    const float* bo        = (const float*)d_in[7];
    const float* ln2_scale = (const float*)d_in[8];
    const float* ln2_bias  = (const float*)d_in[9];
    const float* W1        = (const float*)d_in[10];
    const float* b1        = (const float*)d_in[11];
    const float* W2        = (const float*)d_in[12];
    const float* b2        = (const float*)d_in[13];
    float* out = (float*)d_out;

    bf16 *h, *wqkv, *qkvh, *ctx, *h2, *ff, *wo, *w1, *w2;
    float *x1;
    cudaGetSymbolAddress((void**)&h,    g_h);
    cudaGetSymbolAddress((void**)&wqkv, g_wqkv);
    cudaGetSymbolAddress((void**)&qkvh, g_qkvh);
    cudaGetSymbolAddress((void**)&ctx,  g_ctx);
    cudaGetSymbolAddress((void**)&x1,   g_x1);
    cudaGetSymbolAddress((void**)&h2,   g_h2);
    cudaGetSymbolAddress((void**)&ff,   g_ff);
    cudaGetSymbolAddress((void**)&wo,   g_wo);
    cudaGetSymbolAddress((void**)&w1,   g_w1);
    cudaGetSymbolAddress((void**)&w2,   g_w2);

    cudaFuncSetAttribute(gemm_mma<false,false,false,bf16>,
                         cudaFuncAttributeMaxDynamicSharedMemorySize, GEMM_SMEM);
    cudaFuncSetAttribute(gemm_mma<true,true,false,float>,
                         cudaFuncAttributeMaxDynamicSharedMemorySize, GEMM_SMEM);
    cudaFuncSetAttribute(gemm_mma<true,false,true,bf16>,
                         cudaFuncAttributeMaxDynamicSharedMemorySize, GEMM_SMEM);

    // weight prep: transpose to [N, K] bf16
    qkv_trans<<<dim3(32, 2, 48), 256>>>(Wq, Wk, Wv, wqkv);
    wtrans<<<dim3(32, 32), 256>>>(Wo, wo, DD, DD);
    wtrans<<<dim3(32, 128), 256>>>(W1, w1, DD, FF);
    wtrans<<<dim3(128, 32), 256>>>(W2, w2, FF, DD);

    // LN1 (bf16 out)
    ln_kernel<<<MM, 256>>>(x, ln1_scale, ln1_bias, h);
    // QKV projection -> bf16 (Q pre-scaled via Wq)
    gemm_mma<false,false,false,bf16><<<dim3(QKVN/256, MM/128), 256, GEMM_SMEM>>>(h, wqkv, nullptr, nullptr, qkvh, MM, QKVN, DD);
    // tensor-core flash attention (ctx bf16)
    attn_mma<<<dim3(BB*HH, SS/64), 128>>>(qkvh, ctx);
    // output projection + bias + residual x -> x1 (fp32)
    gemm_mma<true,true,false,float><<<dim3(DD/256, MM/128), 256, GEMM_SMEM>>>(ctx, wo, bo, x, x1, MM, DD, DD);
    // LN2 (bf16 out)
    ln_kernel<<<MM, 256>>>(x1, ln2_scale, ln2_bias, h2);
    // FF1 + relu (bf16 out)
    gemm_mma<true,false,true,bf16><<<dim3(FF/256, MM/128), 256, GEMM_SMEM>>>(h2, w1, b1, nullptr, ff, MM, FF, DD);
    // FF2 + bias + residual x1 -> out (fp32)
    gemm_mma<true,true,false,float><<<dim3(DD/256, MM/128), 256, GEMM_SMEM>>>(ff, w2, b2, x1, out, MM, DD, FF);
}